// round 10
// baseline (speedup 1.0000x reference)
#include <cuda_runtime.h>
#include <cuda_fp16.h>
#include <cstdint>

#define NMAX 100000
#define EMAX 1600000
#define DF 64

// ---------------- device scratch (no allocations allowed) ----------------
__device__ __half g_Kh[NMAX * DF];
__device__ __half g_Qh[NMAX * DF];
__device__ __half g_Vh[NMAX * DF];
__device__ float  g_H[NMAX * DF];   // skip from GEMM, then h = skip + agg (in place)
__device__ int    g_src[EMAX];
__device__ int    g_dst[EMAX];
__device__ int    g_esrc[EMAX];     // src indices grouped by dst (counting sort)
__device__ int    g_cnt[NMAX];
__device__ int    g_off[NMAX + 1];
__device__ int    g_pos[NMAX];
__device__ __half g_Wh[4 * DF * DF];  // fp16 weights, [m][c][k] row-major
__device__ float  g_sum[DF];
__device__ float  g_sumsq[DF];
__device__ int    g_is64;

// ---------------- mma helpers ----------------
__device__ __forceinline__ void ldsm_x4(unsigned* r, uint32_t addr) {
    asm volatile("ldmatrix.sync.aligned.m8n8.x4.shared.b16 {%0,%1,%2,%3}, [%4];\n"
                 : "=r"(r[0]), "=r"(r[1]), "=r"(r[2]), "=r"(r[3]) : "r"(addr));
}
__device__ __forceinline__ void mma16816(float* d, const unsigned* a, const unsigned* b) {
    asm volatile(
        "mma.sync.aligned.m16n8k16.row.col.f32.f16.f16.f32 "
        "{%0,%1,%2,%3}, {%4,%5,%6,%7}, {%8,%9}, {%0,%1,%2,%3};\n"
        : "+f"(d[0]), "+f"(d[1]), "+f"(d[2]), "+f"(d[3])
        : "r"(a[0]), "r"(a[1]), "r"(a[2]), "r"(a[3]), "r"(b[0]), "r"(b[1]));
}

// ---------------- 0: zero counters; detect int64-vs-int32 edge_index ----------------
__global__ void init_kernel(const int* __restrict__ ei32, int e, int n) {
    int gt = blockIdx.x * blockDim.x + threadIdx.x;
    for (int i = gt; i < n; i += gridDim.x * blockDim.x) g_cnt[i] = 0;
    if (gt < DF) { g_sum[gt] = 0.0f; g_sumsq[gt] = 0.0f; }
    if (blockIdx.x == 0) {
        __shared__ int any;
        int t = threadIdx.x;
        if (t == 0) any = 0;
        __syncthreads();
        int nz = 0;
        for (int i = t; i < 1024; i += blockDim.x)
            if (i < e) nz |= ei32[2 * i + 1];
        if (nz) atomicOr(&any, 1);
        __syncthreads();
        if (t == 0) g_is64 = any ? 0 : 1;
    }
}

// ---------------- 1: edge index -> int32 src/dst + dst histogram ----------------
__global__ void hist_kernel(const void* __restrict__ ei, int e) {
    int i = blockIdx.x * blockDim.x + threadIdx.x;
    if (i >= e) return;
    int s, d;
    if (g_is64) {
        const long long* p = (const long long*)ei;
        s = (int)p[i]; d = (int)p[e + i];
    } else {
        const int* p = (const int*)ei;
        s = p[i]; d = p[e + i];
    }
    g_src[i] = s;
    g_dst[i] = d;
    atomicAdd(&g_cnt[d], 1);
}

// ---------------- 2: one-block exclusive scan of g_cnt -> g_off, g_pos ----------------
__global__ void scan_kernel(int n, int e) {
    __shared__ int s_tot[1024];
    int t = threadIdx.x;
    int chunk = (n + 1023) >> 10;
    int base = t * chunk;
    int sum = 0;
    for (int j = 0; j < chunk; j++) {
        int i = base + j;
        if (i < n) sum += g_cnt[i];
    }
    s_tot[t] = sum;
    __syncthreads();
    for (int d = 1; d < 1024; d <<= 1) {
        int v = (t >= d) ? s_tot[t - d] : 0;
        __syncthreads();
        s_tot[t] += v;
        __syncthreads();
    }
    int run = s_tot[t] - sum;  // exclusive prefix for this chunk
    for (int j = 0; j < chunk; j++) {
        int i = base + j;
        if (i < n) {
            g_off[i] = run;
            g_pos[i] = run;
            run += g_cnt[i];
        }
    }
    if (t == 0) g_off[n] = e;
}

// ---------------- 3: scatter src into dst-grouped order ----------------
__global__ void scatter_kernel(int e) {
    int i = blockIdx.x * blockDim.x + threadIdx.x;
    if (i >= e) return;
    int slot = atomicAdd(&g_pos[g_dst[i]], 1);
    g_esrc[slot] = g_src[i];
}

// ---------------- 4: weights -> fp16 ----------------
__global__ void convw_kernel(const float* __restrict__ Wk, const float* __restrict__ Wq,
                             const float* __restrict__ Wv, const float* __restrict__ Ws) {
    int idx = blockIdx.x * blockDim.x + threadIdx.x;
    if (idx >= 4 * DF * DF) return;
    int m = idx >> 12;
    int i = idx & 4095;
    const float* W = (m == 0) ? Wk : (m == 1) ? Wq : (m == 2) ? Wv : Ws;
    g_Wh[idx] = __float2half(W[i]);
}

// ---------------- 5: tensor-core GEMM: all 4 matrices, one launch, one sync ------------
#define GEMM_SMEM ((128 * 72 + 4 * 64 * 72) * 2)

__global__ void __launch_bounds__(256) gemm_kernel(const float* __restrict__ x,
                                                   const float* __restrict__ bk,
                                                   const float* __restrict__ bq,
                                                   const float* __restrict__ bv,
                                                   const float* __restrict__ bs,
                                                   int n) {
    extern __shared__ __half smh[];
    __half* xs = smh;                 // [128][72]
    __half* ws = smh + 128 * 72;      // [4][64][72]
    int t = threadIdx.x;
    int lane = t & 31, w = t >> 5;
    int row0 = blockIdx.x * 128;

    for (int idx = t; idx < 128 * 16; idx += 256) {
        int r = idx >> 4, k4 = idx & 15;
        float4 v = make_float4(0.f, 0.f, 0.f, 0.f);
        if (row0 + r < n)
            v = reinterpret_cast<const float4*>(x + (size_t)(row0 + r) * DF)[k4];
        __half2 h0 = __floats2half2_rn(v.x, v.y);
        __half2 h1 = __floats2half2_rn(v.z, v.w);
        uint2 u;
        u.x = reinterpret_cast<unsigned&>(h0);
        u.y = reinterpret_cast<unsigned&>(h1);
        *reinterpret_cast<uint2*>(&xs[r * 72 + k4 * 4]) = u;
    }
    for (int idx = t; idx < 4 * 64 * 8; idx += 256) {
        int mr = idx >> 3, k8 = idx & 7;
        uint4 v = *reinterpret_cast<const uint4*>(&g_Wh[mr * DF + k8 * 8]);
        *reinterpret_cast<uint4*>(&ws[mr * 72 + k8 * 8]) = v;
    }
    __syncthreads();

    int rt = w >> 1, ch = w & 1;
    int a_row = lane & 15, a_ch = lane >> 4;
    int b_row = lane & 7, b_ch = (lane >> 3) & 1, b_nt = lane >> 4;

    unsigned a[2][4][4];
#pragma unroll
    for (int i = 0; i < 2; i++)
#pragma unroll
        for (int ks = 0; ks < 4; ks++) {
            uint32_t addr = (uint32_t)__cvta_generic_to_shared(
                &xs[(rt * 32 + 16 * i + a_row) * 72 + ks * 16 + a_ch * 8]);
            ldsm_x4(a[i][ks], addr);
        }

    int ra = (lane >> 2);
    int coff = (lane & 3) * 2;

#pragma unroll
    for (int m = 0; m < 4; m++) {
        float acc[2][4][4];
#pragma unroll
        for (int i = 0; i < 2; i++)
#pragma unroll
            for (int j = 0; j < 4; j++)
#pragma unroll
                for (int c = 0; c < 4; c++) acc[i][j][c] = 0.0f;

#pragma unroll
        for (int ks = 0; ks < 4; ks++) {
            unsigned b[4][2];
#pragma unroll
            for (int h = 0; h < 2; h++) {
                uint32_t addr = (uint32_t)__cvta_generic_to_shared(
                    &ws[(m * 64 + ch * 32 + h * 16 + 8 * b_nt + b_row) * 72 +
                        ks * 16 + b_ch * 8]);
                unsigned r4[4];
                ldsm_x4(r4, addr);
                b[2 * h][0] = r4[0];     b[2 * h][1] = r4[1];
                b[2 * h + 1][0] = r4[2]; b[2 * h + 1][1] = r4[3];
            }
#pragma unroll
            for (int i = 0; i < 2; i++)
#pragma unroll
                for (int j = 0; j < 4; j++)
                    mma16816(acc[i][j], a[i][ks], b[j]);
        }

        const float* bp = (m == 0) ? bk : (m == 1) ? bq : (m == 2) ? bv : bs;
        float bb[4][2];
#pragma unroll
        for (int j = 0; j < 4; j++) {
            int col = ch * 32 + j * 8 + coff;
            bb[j][0] = __ldg(&bp[col]);
            bb[j][1] = __ldg(&bp[col + 1]);
        }
#pragma unroll
        for (int i = 0; i < 2; i++) {
            int r0g = row0 + rt * 32 + 16 * i + ra;
#pragma unroll
            for (int j = 0; j < 4; j++) {
                int col = ch * 32 + j * 8 + coff;
                float v0 = acc[i][j][0] + bb[j][0], v1 = acc[i][j][1] + bb[j][1];
                float v2 = acc[i][j][2] + bb[j][0], v3 = acc[i][j][3] + bb[j][1];
                if (m < 3) {
                    __half* outh = (m == 0) ? g_Kh : (m == 1) ? g_Qh : g_Vh;
                    if (r0g < n)
                        *reinterpret_cast<__half2*>(outh + (size_t)r0g * DF + col) =
                            __floats2half2_rn(v0, v1);
                    if (r0g + 8 < n)
                        *reinterpret_cast<__half2*>(outh + (size_t)(r0g + 8) * DF + col) =
                            __floats2half2_rn(v2, v3);
                } else {
                    if (r0g < n)
                        *reinterpret_cast<float2*>(g_H + (size_t)r0g * DF + col) =
                            make_float2(v0, v1);
                    if (r0g + 8 < n)
                        *reinterpret_cast<float2*>(g_H + (size_t)(r0g + 8) * DF + col) =
                            make_float2(v2, v3);
                }
            }
        }
    }
}

// ---------------- 6: dst-grouped aggregation + skip + inline BN stats ----------------
// 8 threads per dst node (block = 32 nodes). k[dst] in regs; loop over grouped
// sources: gather q/v rows (256B/edge), gate, accumulate fp32 in regs. One
// non-atomic g_H read-modify-write per node. BN sum/sumsq reduced via shfl ->
// smem -> one global atomic per column per block.
__global__ void __launch_bounds__(256) agg_kernel(int n) {
    __shared__ float s_sum[64], s_sq[64];
    int t = threadIdx.x;
    if (t < 64) { s_sum[t] = 0.0f; s_sq[t] = 0.0f; }
    __syncthreads();

    int lane8 = t & 7;
    int v = blockIdx.x * 32 + (t >> 3);
    float hval[8];
#pragma unroll
    for (int j = 0; j < 8; j++) hval[j] = 0.0f;

    if (v < n) {
        uint4 kr = *(reinterpret_cast<const uint4*>(g_Kh) + (size_t)v * 8 + lane8);
        const __half2* kh = reinterpret_cast<const __half2*>(&kr);
        float kf[8];
#pragma unroll
        for (int p = 0; p < 4; p++) {
            float2 f = __half22float2(kh[p]);
            kf[2 * p] = f.x; kf[2 * p + 1] = f.y;
        }
        float acc[8];
#pragma unroll
        for (int j = 0; j < 8; j++) acc[j] = 0.0f;

        int beg = g_off[v], end = g_off[v + 1];
        for (int j = beg; j < end; j++) {
            int s = g_esrc[j];
            uint4 qr = __ldg(reinterpret_cast<const uint4*>(g_Qh) + (size_t)s * 8 + lane8);
            uint4 vr = __ldg(reinterpret_cast<const uint4*>(g_Vh) + (size_t)s * 8 + lane8);
            const __half2* qh = reinterpret_cast<const __half2*>(&qr);
            const __half2* vh = reinterpret_cast<const __half2*>(&vr);
#pragma unroll
            for (int p = 0; p < 4; p++) {
                float2 qf = __half22float2(qh[p]);
                float2 vf = __half22float2(vh[p]);
                acc[2 * p]     += __fdividef(vf.x, 1.0f + __expf(-(kf[2 * p] + qf.x)));
                acc[2 * p + 1] += __fdividef(vf.y, 1.0f + __expf(-(kf[2 * p + 1] + qf.y)));
            }
        }
        // h = skip + agg (in place, exclusive to this group)
        float4* hp = reinterpret_cast<float4*>(g_H) + (size_t)v * 16 + lane8 * 2;
        float4 h0 = hp[0], h1 = hp[1];
        h0.x += acc[0]; h0.y += acc[1]; h0.z += acc[2]; h0.w += acc[3];
        h1.x += acc[4]; h1.y += acc[5]; h1.z += acc[6]; h1.w += acc[7];
        hp[0] = h0; hp[1] = h1;
        hval[0] = h0.x; hval[1] = h0.y; hval[2] = h0.z; hval[3] = h0.w;
        hval[4] = h1.x; hval[5] = h1.y; hval[6] = h1.z; hval[7] = h1.w;
    }

    // BN stats: reduce the 4 groups of each warp via shfl, then smem, then global.
#pragma unroll
    for (int j = 0; j < 8; j++) {
        float s1 = hval[j];
        float s2 = hval[j] * hval[j];
        s1 += __shfl_down_sync(0xffffffffu, s1, 16);
        s2 += __shfl_down_sync(0xffffffffu, s2, 16);
        s1 += __shfl_down_sync(0xffffffffu, s1, 8);
        s2 += __shfl_down_sync(0xffffffffu, s2, 8);
        if ((t & 31) < 8) {
            atomicAdd(&s_sum[lane8 * 8 + j], s1);
            atomicAdd(&s_sq[lane8 * 8 + j], s2);
        }
    }
    __syncthreads();
    if (t < 64) {
        atomicAdd(&g_sum[t], s_sum[t]);
        atomicAdd(&g_sumsq[t], s_sq[t]);
    }
}

// ---------------- 7: BN affine + ReLU + residual ----------------
__global__ void __launch_bounds__(256) out_kernel(const float* __restrict__ x,
                                                  const float* __restrict__ gamma,
                                                  const float* __restrict__ beta,
                                                  float* __restrict__ out, int n) {
    __shared__ float sc[64], sh[64];
    int t = threadIdx.x;
    if (t < 64) {
        float invn = 1.0f / (float)n;
        float mean = g_sum[t] * invn;
        float var = g_sumsq[t] * invn - mean * mean;
        float s = gamma[t] * rsqrtf(var + 1e-5f);
        sc[t] = s;
        sh[t] = beta[t] - mean * s;
    }
    __syncthreads();
    const float4* H4 = reinterpret_cast<const float4*>(g_H);
    const float4* X4 = reinterpret_cast<const float4*>(x);
    float4* O4 = reinterpret_cast<float4*>(out);
    int total = n * 16;
    for (int i = blockIdx.x * blockDim.x + t; i < total; i += gridDim.x * blockDim.x) {
        int col = (i & 15) * 4;
        float4 h = H4[i];
        float4 xv = X4[i];
        float4 o;
        o.x = fmaxf(h.x * sc[col + 0] + sh[col + 0], 0.0f) + xv.x;
        o.y = fmaxf(h.y * sc[col + 1] + sh[col + 1], 0.0f) + xv.y;
        o.z = fmaxf(h.z * sc[col + 2] + sh[col + 2], 0.0f) + xv.z;
        o.w = fmaxf(h.w * sc[col + 3] + sh[col + 3], 0.0f) + xv.w;
        O4[i] = o;
    }
}

// ---------------- launch ----------------
extern "C" void kernel_launch(void* const* d_in, const int* in_sizes, int n_in,
                              void* d_out, int out_size) {
    const float* x     = (const float*)d_in[0];
    const void*  ei    = d_in[1];
    const float* Wk    = (const float*)d_in[2];
    const float* bk    = (const float*)d_in[3];
    const float* Wq    = (const float*)d_in[4];
    const float* bq    = (const float*)d_in[5];
    const float* Wv    = (const float*)d_in[6];
    const float* bv    = (const float*)d_in[7];
    const float* Ws    = (const float*)d_in[8];
    const float* bs    = (const float*)d_in[9];
    const float* gamma = (const float*)d_in[10];
    const float* beta  = (const float*)d_in[11];

    int n = in_sizes[0] / DF;
    int e = in_sizes[1] / 2;

    static bool attr_done = false;
    if (!attr_done) {
        cudaFuncSetAttribute(gemm_kernel, cudaFuncAttributeMaxDynamicSharedMemorySize,
                             GEMM_SMEM);
        attr_done = true;
    }

    init_kernel<<<200, 256>>>((const int*)ei, e, n);
    hist_kernel<<<(e + 255) / 256, 256>>>(ei, e);
    scan_kernel<<<1, 1024>>>(n, e);
    scatter_kernel<<<(e + 255) / 256, 256>>>(e);
    convw_kernel<<<(4 * DF * DF + 255) / 256, 256>>>(Wk, Wq, Wv, Ws);

    gemm_kernel<<<(n + 127) / 128, 256, GEMM_SMEM>>>(x, bk, bq, bv, bs, n);

    agg_kernel<<<(n + 31) / 32, 256>>>(n);
    out_kernel<<<2048, 256>>>(x, gamma, beta, (float*)d_out, n);
}

// round 11
// speedup vs baseline: 1.7942x; 1.7942x over previous
#include <cuda_runtime.h>
#include <cuda_fp16.h>
#include <cstdint>

#define NMAX 100000
#define EMAX 1600000
#define DF 64

// ---------------- device scratch (no allocations allowed) ----------------
__device__ __half g_Kh[NMAX * DF];
__device__ __half g_Qh[NMAX * DF];
__device__ __half g_Vh[NMAX * DF];
__device__ float  g_H[NMAX * DF];   // fp32: skip from GEMM, then += messages
__device__ int    g_src[EMAX];
__device__ int    g_dst[EMAX];
__device__ __half g_Wh[4 * DF * DF];  // fp16 weights, [m][c][k] row-major
__device__ float  g_sum[DF];
__device__ float  g_sumsq[DF];
__device__ int    g_is64;

// ---------------- mma helpers ----------------
__device__ __forceinline__ void ldsm_x4(unsigned* r, uint32_t addr) {
    asm volatile("ldmatrix.sync.aligned.m8n8.x4.shared.b16 {%0,%1,%2,%3}, [%4];\n"
                 : "=r"(r[0]), "=r"(r[1]), "=r"(r[2]), "=r"(r[3]) : "r"(addr));
}
__device__ __forceinline__ void mma16816(float* d, const unsigned* a, const unsigned* b) {
    asm volatile(
        "mma.sync.aligned.m16n8k16.row.col.f32.f16.f16.f32 "
        "{%0,%1,%2,%3}, {%4,%5,%6,%7}, {%8,%9}, {%0,%1,%2,%3};\n"
        : "+f"(d[0]), "+f"(d[1]), "+f"(d[2]), "+f"(d[3])
        : "r"(a[0]), "r"(a[1]), "r"(a[2]), "r"(a[3]), "r"(b[0]), "r"(b[1]));
}

// ---------------- 0: detect int64-vs-int32 edge_index; zero BN sums ----------------
__global__ void init_kernel(const int* __restrict__ ei32, int e) {
    __shared__ int any;
    int t = threadIdx.x;
    if (t == 0) any = 0;
    if (t < DF) { g_sum[t] = 0.0f; g_sumsq[t] = 0.0f; }
    __syncthreads();
    int nz = 0;
    for (int i = t; i < 1024; i += blockDim.x) {
        if (i < e) nz |= ei32[2 * i + 1];
    }
    if (nz) atomicOr(&any, 1);
    __syncthreads();
    if (t == 0) g_is64 = any ? 0 : 1;
}

// ---------------- 1: edge index -> int32 src/dst ----------------
__global__ void convert_kernel(const void* __restrict__ ei, int e) {
    int i = blockIdx.x * blockDim.x + threadIdx.x;
    if (i >= e) return;
    if (g_is64) {
        const long long* p = (const long long*)ei;
        g_src[i] = (int)p[i];
        g_dst[i] = (int)p[e + i];
    } else {
        const int* p = (const int*)ei;
        g_src[i] = p[i];
        g_dst[i] = p[e + i];
    }
}

// ---------------- 2: weights -> fp16 ----------------
__global__ void convw_kernel(const float* __restrict__ Wk, const float* __restrict__ Wq,
                             const float* __restrict__ Wv, const float* __restrict__ Ws) {
    int idx = blockIdx.x * blockDim.x + threadIdx.x;
    if (idx >= 4 * DF * DF) return;
    int m = idx >> 12;
    int i = idx & 4095;
    const float* W = (m == 0) ? Wk : (m == 1) ? Wq : (m == 2) ? Wv : Ws;
    g_Wh[idx] = __float2half(W[i]);
}

// ---------------- 3: tensor-core GEMM: all 4 matrices, one launch, one sync ------------
// Block: 64 rows, 256 threads (8 warps). Smaller tile than before -> ~80 regs and
// 46 KB smem -> 3 blocks/SM (24 warps, ~50% occ) for latency hiding.
// Warp task = 16 rows x 32 cols for all 4 matrices: rt = w>>1, ch = w&1.
// A-fragments loaded ONCE, reused across the 4 matrices.
#define GEMM_SMEM ((64 * 72 + 4 * 64 * 72) * 2)

__global__ void __launch_bounds__(256) gemm_kernel(const float* __restrict__ x,
                                                   const float* __restrict__ bk,
                                                   const float* __restrict__ bq,
                                                   const float* __restrict__ bv,
                                                   const float* __restrict__ bs,
                                                   int n) {
    extern __shared__ __half smh[];
    __half* xs = smh;                 // [64][72]
    __half* ws = smh + 64 * 72;       // [4][64][72]
    int t = threadIdx.x;
    int lane = t & 31, w = t >> 5;
    int row0 = blockIdx.x * 64;

    // Stage x -> fp16 (zero-fill OOB rows)
    for (int idx = t; idx < 64 * 16; idx += 256) {
        int r = idx >> 4, k4 = idx & 15;
        float4 v = make_float4(0.f, 0.f, 0.f, 0.f);
        if (row0 + r < n)
            v = reinterpret_cast<const float4*>(x + (size_t)(row0 + r) * DF)[k4];
        __half2 h0 = __floats2half2_rn(v.x, v.y);
        __half2 h1 = __floats2half2_rn(v.z, v.w);
        uint2 u;
        u.x = reinterpret_cast<unsigned&>(h0);
        u.y = reinterpret_cast<unsigned&>(h1);
        *reinterpret_cast<uint2*>(&xs[r * 72 + k4 * 4]) = u;
    }
    // Stage all 4 weight matrices
    for (int idx = t; idx < 4 * 64 * 8; idx += 256) {
        int mr = idx >> 3, k8 = idx & 7;
        uint4 v = *reinterpret_cast<const uint4*>(&g_Wh[mr * DF + k8 * 8]);
        *reinterpret_cast<uint4*>(&ws[mr * 72 + k8 * 8]) = v;
    }
    __syncthreads();

    int rt = w >> 1;          // row-group 0..3 (16 rows each)
    int ch = w & 1;           // col-half 0..1 (32 cols each)
    int a_row = lane & 15;
    int a_ch  = lane >> 4;
    int b_row = lane & 7;
    int b_ch  = (lane >> 3) & 1;
    int b_nt  = lane >> 4;

    // A fragments: 1 m16 tile x 4 ks, loaded once, reused for all 4 matrices
    unsigned a[4][4];
#pragma unroll
    for (int ks = 0; ks < 4; ks++) {
        uint32_t addr = (uint32_t)__cvta_generic_to_shared(
            &xs[(rt * 16 + a_row) * 72 + ks * 16 + a_ch * 8]);
        ldsm_x4(a[ks], addr);
    }

    int ra = (lane >> 2);
    int coff = (lane & 3) * 2;

#pragma unroll
    for (int m = 0; m < 4; m++) {
        float acc[4][4];
#pragma unroll
        for (int j = 0; j < 4; j++)
#pragma unroll
            for (int c = 0; c < 4; c++) acc[j][c] = 0.0f;

#pragma unroll
        for (int ks = 0; ks < 4; ks++) {
            unsigned b[4][2];
#pragma unroll
            for (int h = 0; h < 2; h++) {
                uint32_t addr = (uint32_t)__cvta_generic_to_shared(
                    &ws[(m * 64 + ch * 32 + h * 16 + 8 * b_nt + b_row) * 72 +
                        ks * 16 + b_ch * 8]);
                unsigned r4[4];
                ldsm_x4(r4, addr);
                b[2 * h][0] = r4[0];     b[2 * h][1] = r4[1];
                b[2 * h + 1][0] = r4[2]; b[2 * h + 1][1] = r4[3];
            }
#pragma unroll
            for (int j = 0; j < 4; j++)
                mma16816(acc[j], a[ks], b[j]);
        }

        const float* bp = (m == 0) ? bk : (m == 1) ? bq : (m == 2) ? bv : bs;
        int r0g = row0 + rt * 16 + ra;
#pragma unroll
        for (int j = 0; j < 4; j++) {
            int col = ch * 32 + j * 8 + coff;
            float bb0 = __ldg(&bp[col]);
            float bb1 = __ldg(&bp[col + 1]);
            float v0 = acc[j][0] + bb0, v1 = acc[j][1] + bb1;
            float v2 = acc[j][2] + bb0, v3 = acc[j][3] + bb1;
            if (m < 3) {
                __half* outh = (m == 0) ? g_Kh : (m == 1) ? g_Qh : g_Vh;
                if (r0g < n)
                    *reinterpret_cast<__half2*>(outh + (size_t)r0g * DF + col) =
                        __floats2half2_rn(v0, v1);
                if (r0g + 8 < n)
                    *reinterpret_cast<__half2*>(outh + (size_t)(r0g + 8) * DF + col) =
                        __floats2half2_rn(v2, v3);
            } else {
                if (r0g < n)
                    *reinterpret_cast<float2*>(g_H + (size_t)r0g * DF + col) =
                        make_float2(v0, v1);
                if (r0g + 8 < n)
                    *reinterpret_cast<float2*>(g_H + (size_t)(r0g + 8) * DF + col) =
                        make_float2(v2, v3);
            }
        }
    }
}

// ---------------- 4: edge gather (fp16) + gate + fp32 vector-atomic scatter --------------
// 8 threads per edge-PAIR-chunk: each thread handles features c*8..c*8+7 of TWO
// consecutive edges. 6 gathers issued before any compute -> MLP 6 per thread.
__global__ void __launch_bounds__(256) edge_kernel(int e) {
    int idx = blockIdx.x * blockDim.x + threadIdx.x;
    int pair = idx >> 3;
    int c = idx & 7;
    int ed0 = pair * 2;
    if (ed0 >= e) return;
    int ed1 = ed0 + 1;
    bool has1 = (ed1 < e);

    int s0 = g_src[ed0], d0 = g_dst[ed0];
    int s1 = has1 ? g_src[ed1] : s0;
    int d1 = has1 ? g_dst[ed1] : d0;

    const uint4* Kp = reinterpret_cast<const uint4*>(g_Kh);
    const uint4* Qp = reinterpret_cast<const uint4*>(g_Qh);
    const uint4* Vp = reinterpret_cast<const uint4*>(g_Vh);
    // issue all 6 gathers up front
    uint4 kr0 = __ldg(&Kp[(size_t)d0 * 8 + c]);
    uint4 qr0 = __ldg(&Qp[(size_t)s0 * 8 + c]);
    uint4 vr0 = __ldg(&Vp[(size_t)s0 * 8 + c]);
    uint4 kr1 = __ldg(&Kp[(size_t)d1 * 8 + c]);
    uint4 qr1 = __ldg(&Qp[(size_t)s1 * 8 + c]);
    uint4 vr1 = __ldg(&Vp[(size_t)s1 * 8 + c]);

    {
        const __half2* kh = reinterpret_cast<const __half2*>(&kr0);
        const __half2* qh = reinterpret_cast<const __half2*>(&qr0);
        const __half2* vh = reinterpret_cast<const __half2*>(&vr0);
        float msg[8];
#pragma unroll
        for (int p = 0; p < 4; p++) {
            float2 kf = __half22float2(kh[p]);
            float2 qf = __half22float2(qh[p]);
            float2 vf = __half22float2(vh[p]);
            msg[2 * p]     = __fdividef(vf.x, 1.0f + __expf(-(kf.x + qf.x)));
            msg[2 * p + 1] = __fdividef(vf.y, 1.0f + __expf(-(kf.y + qf.y)));
        }
        float4* hp = reinterpret_cast<float4*>(g_H + (size_t)d0 * DF + c * 8);
        atomicAdd(hp,     make_float4(msg[0], msg[1], msg[2], msg[3]));
        atomicAdd(hp + 1, make_float4(msg[4], msg[5], msg[6], msg[7]));
    }
    if (has1) {
        const __half2* kh = reinterpret_cast<const __half2*>(&kr1);
        const __half2* qh = reinterpret_cast<const __half2*>(&qr1);
        const __half2* vh = reinterpret_cast<const __half2*>(&vr1);
        float msg[8];
#pragma unroll
        for (int p = 0; p < 4; p++) {
            float2 kf = __half22float2(kh[p]);
            float2 qf = __half22float2(qh[p]);
            float2 vf = __half22float2(vh[p]);
            msg[2 * p]     = __fdividef(vf.x, 1.0f + __expf(-(kf.x + qf.x)));
            msg[2 * p + 1] = __fdividef(vf.y, 1.0f + __expf(-(kf.y + qf.y)));
        }
        float4* hp = reinterpret_cast<float4*>(g_H + (size_t)d1 * DF + c * 8);
        atomicAdd(hp,     make_float4(msg[0], msg[1], msg[2], msg[3]));
        atomicAdd(hp + 1, make_float4(msg[4], msg[5], msg[6], msg[7]));
    }
}

// ---------------- 5: BatchNorm statistics (per-column sum / sumsq) ----------------
__global__ void __launch_bounds__(256) stats_kernel(int n) {
    __shared__ float ss[256], ss2[256];
    int t = threadIdx.x;
    int col = t & 63;
    int q = t >> 6;  // 0..3
    float s = 0.0f, s2 = 0.0f;
    for (int r = blockIdx.x * 4 + q; r < n; r += gridDim.x * 4) {
        float v = g_H[(size_t)r * DF + col];
        s += v;
        s2 += v * v;
    }
    ss[t] = s; ss2[t] = s2;
    __syncthreads();
    if (t < 64) {
        float ts = ss[t] + ss[t + 64] + ss[t + 128] + ss[t + 192];
        float ts2 = ss2[t] + ss2[t + 64] + ss2[t + 128] + ss2[t + 192];
        atomicAdd(&g_sum[t], ts);
        atomicAdd(&g_sumsq[t], ts2);
    }
}

// ---------------- 6: BN affine + ReLU + residual ----------------
__global__ void __launch_bounds__(256) out_kernel(const float* __restrict__ x,
                                                  const float* __restrict__ gamma,
                                                  const float* __restrict__ beta,
                                                  float* __restrict__ out, int n) {
    __shared__ float sc[64], sh[64];
    int t = threadIdx.x;
    if (t < 64) {
        float invn = 1.0f / (float)n;
        float mean = g_sum[t] * invn;
        float var = g_sumsq[t] * invn - mean * mean;
        float s = gamma[t] * rsqrtf(var + 1e-5f);
        sc[t] = s;
        sh[t] = beta[t] - mean * s;
    }
    __syncthreads();
    const float4* H4 = reinterpret_cast<const float4*>(g_H);
    const float4* X4 = reinterpret_cast<const float4*>(x);
    float4* O4 = reinterpret_cast<float4*>(out);
    int total = n * 16;
    for (int i = blockIdx.x * blockDim.x + t; i < total; i += gridDim.x * blockDim.x) {
        int col = (i & 15) * 4;
        float4 h = H4[i];
        float4 xv = X4[i];
        float4 o;
        o.x = fmaxf(h.x * sc[col + 0] + sh[col + 0], 0.0f) + xv.x;
        o.y = fmaxf(h.y * sc[col + 1] + sh[col + 1], 0.0f) + xv.y;
        o.z = fmaxf(h.z * sc[col + 2] + sh[col + 2], 0.0f) + xv.z;
        o.w = fmaxf(h.w * sc[col + 3] + sh[col + 3], 0.0f) + xv.w;
        O4[i] = o;
    }
}

// ---------------- launch ----------------
extern "C" void kernel_launch(void* const* d_in, const int* in_sizes, int n_in,
                              void* d_out, int out_size) {
    const float* x     = (const float*)d_in[0];
    const void*  ei    = d_in[1];
    const float* Wk    = (const float*)d_in[2];
    const float* bk    = (const float*)d_in[3];
    const float* Wq    = (const float*)d_in[4];
    const float* bq    = (const float*)d_in[5];
    const float* Wv    = (const float*)d_in[6];
    const float* bv    = (const float*)d_in[7];
    const float* Ws    = (const float*)d_in[8];
    const float* bs    = (const float*)d_in[9];
    const float* gamma = (const float*)d_in[10];
    const float* beta  = (const float*)d_in[11];

    int n = in_sizes[0] / DF;
    int e = in_sizes[1] / 2;

    static bool attr_done = false;
    if (!attr_done) {
        cudaFuncSetAttribute(gemm_kernel, cudaFuncAttributeMaxDynamicSharedMemorySize,
                             GEMM_SMEM);
        attr_done = true;
    }

    init_kernel<<<1, 256>>>((const int*)ei, e);
    convert_kernel<<<(e + 255) / 256, 256>>>(ei, e);
    convw_kernel<<<(4 * DF * DF + 255) / 256, 256>>>(Wk, Wq, Wv, Ws);

    gemm_kernel<<<(n + 63) / 64, 256, GEMM_SMEM>>>(x, bk, bq, bv, bs, n);

    int pairs = (e + 1) / 2;
    edge_kernel<<<(pairs * 8 + 255) / 256, 256>>>(e);
    stats_kernel<<<1024, 256>>>(n);
    out_kernel<<<2048, 256>>>(x, gamma, beta, (float*)d_out, n);
}

// round 13
// speedup vs baseline: 1.8738x; 1.0444x over previous
#include <cuda_runtime.h>
#include <cuda_fp16.h>
#include <cstdint>

#define NMAX 100000
#define EMAX 1600000
#define DF 64

// ---------------- device scratch (no allocations allowed) ----------------
__device__ __half g_Kh[NMAX * DF];
__device__ __half g_Qh[NMAX * DF];
__device__ __half g_Vh[NMAX * DF];
__device__ float  g_H[NMAX * DF];   // fp32: skip from GEMM, then += messages
__device__ __half g_Wh[4 * DF * DF];  // fp16 weights, [m][c][k] row-major
__device__ float  g_sum[DF];
__device__ float  g_sumsq[DF];
__device__ int    g_is64;

// ---------------- mma helpers ----------------
__device__ __forceinline__ void ldsm_x4(unsigned* r, uint32_t addr) {
    asm volatile("ldmatrix.sync.aligned.m8n8.x4.shared.b16 {%0,%1,%2,%3}, [%4];\n"
                 : "=r"(r[0]), "=r"(r[1]), "=r"(r[2]), "=r"(r[3]) : "r"(addr));
}
__device__ __forceinline__ void mma16816(float* d, const unsigned* a, const unsigned* b) {
    asm volatile(
        "mma.sync.aligned.m16n8k16.row.col.f32.f16.f16.f32 "
        "{%0,%1,%2,%3}, {%4,%5,%6,%7}, {%8,%9}, {%0,%1,%2,%3};\n"
        : "+f"(d[0]), "+f"(d[1]), "+f"(d[2]), "+f"(d[3])
        : "r"(a[0]), "r"(a[1]), "r"(a[2]), "r"(a[3]), "r"(b[0]), "r"(b[1]));
}

// ---------------- 0: detect int64-vs-int32 edge_index; zero BN sums ----------------
__global__ void init_kernel(const int* __restrict__ ei32, int e) {
    __shared__ int any;
    int t = threadIdx.x;
    if (t == 0) any = 0;
    if (t < DF) { g_sum[t] = 0.0f; g_sumsq[t] = 0.0f; }
    __syncthreads();
    int nz = 0;
    for (int i = t; i < 1024; i += blockDim.x) {
        if (i < e) nz |= ei32[2 * i + 1];
    }
    if (nz) atomicOr(&any, 1);
    __syncthreads();
    if (t == 0) g_is64 = any ? 0 : 1;
}

// ---------------- 1: weights -> fp16 ----------------
__global__ void convw_kernel(const float* __restrict__ Wk, const float* __restrict__ Wq,
                             const float* __restrict__ Wv, const float* __restrict__ Ws) {
    int idx = blockIdx.x * blockDim.x + threadIdx.x;
    if (idx >= 4 * DF * DF) return;
    int m = idx >> 12;
    int i = idx & 4095;
    const float* W = (m == 0) ? Wk : (m == 1) ? Wq : (m == 2) ? Wv : Ws;
    g_Wh[idx] = __float2half(W[i]);
}

// ---------------- 2: tensor-core GEMM: all 4 matrices, one launch, one sync ------------
// Block: 128 rows staged, processed as two 64-row halves reusing the staged
// weights. 256 threads (8 warps); warp task per half = 16 rows x 32 cols across
// all 4 matrices (rt = w>>1, ch = w&1). A-fragments loaded once per half, reused
// for the 4 matrices. ~58 regs + 55.3 KB smem -> 4 blocks/SM (~67% occ).
#define GEMM_SMEM ((128 * 72 + 4 * 64 * 72) * 2)

__global__ void __launch_bounds__(256) gemm_kernel(const float* __restrict__ x,
                                                   const float* __restrict__ bk,
                                                   const float* __restrict__ bq,
                                                   const float* __restrict__ bv,
                                                   const float* __restrict__ bs,
                                                   int n) {
    extern __shared__ __half smh[];
    __half* xs = smh;                 // [128][72]
    __half* ws = smh + 128 * 72;      // [4][64][72]
    int t = threadIdx.x;
    int lane = t & 31, w = t >> 5;
    int row0 = blockIdx.x * 128;

    // Stage x rows (128) -> fp16 (zero-fill OOB)
    for (int idx = t; idx < 128 * 16; idx += 256) {
        int r = idx >> 4, k4 = idx & 15;
        float4 v = make_float4(0.f, 0.f, 0.f, 0.f);
        if (row0 + r < n)
            v = reinterpret_cast<const float4*>(x + (size_t)(row0 + r) * DF)[k4];
        __half2 h0 = __floats2half2_rn(v.x, v.y);
        __half2 h1 = __floats2half2_rn(v.z, v.w);
        uint2 u;
        u.x = reinterpret_cast<unsigned&>(h0);
        u.y = reinterpret_cast<unsigned&>(h1);
        *reinterpret_cast<uint2*>(&xs[r * 72 + k4 * 4]) = u;
    }
    // Stage all 4 weight matrices
    for (int idx = t; idx < 4 * 64 * 8; idx += 256) {
        int mr = idx >> 3, k8 = idx & 7;
        uint4 v = *reinterpret_cast<const uint4*>(&g_Wh[mr * DF + k8 * 8]);
        *reinterpret_cast<uint4*>(&ws[mr * 72 + k8 * 8]) = v;
    }
    __syncthreads();

    int rt = w >> 1;          // row-group 0..3 (16 rows each within a half)
    int ch = w & 1;           // col-half 0..1 (32 cols each)
    int a_row = lane & 15;
    int a_ch  = lane >> 4;
    int b_row = lane & 7;
    int b_ch  = (lane >> 3) & 1;
    int b_nt  = lane >> 4;
    int ra = (lane >> 2);
    int coff = (lane & 3) * 2;

    for (int hh = 0; hh < 2; hh++) {
        int rbase = hh * 64 + rt * 16;

        // A fragments for this half: 1 m16 tile x 4 ks, reused for all 4 matrices
        unsigned a[4][4];
#pragma unroll
        for (int ks = 0; ks < 4; ks++) {
            uint32_t addr = (uint32_t)__cvta_generic_to_shared(
                &xs[(rbase + a_row) * 72 + ks * 16 + a_ch * 8]);
            ldsm_x4(a[ks], addr);
        }

#pragma unroll
        for (int m = 0; m < 4; m++) {
            float acc[4][4];
#pragma unroll
            for (int j = 0; j < 4; j++)
#pragma unroll
                for (int c = 0; c < 4; c++) acc[j][c] = 0.0f;

#pragma unroll
            for (int ks = 0; ks < 4; ks++) {
                unsigned b[4][2];
#pragma unroll
                for (int h = 0; h < 2; h++) {
                    uint32_t addr = (uint32_t)__cvta_generic_to_shared(
                        &ws[(m * 64 + ch * 32 + h * 16 + 8 * b_nt + b_row) * 72 +
                            ks * 16 + b_ch * 8]);
                    unsigned r4[4];
                    ldsm_x4(r4, addr);
                    b[2 * h][0] = r4[0];     b[2 * h][1] = r4[1];
                    b[2 * h + 1][0] = r4[2]; b[2 * h + 1][1] = r4[3];
                }
#pragma unroll
                for (int j = 0; j < 4; j++)
                    mma16816(acc[j], a[ks], b[j]);
            }

            const float* bp = (m == 0) ? bk : (m == 1) ? bq : (m == 2) ? bv : bs;
            int r0g = row0 + rbase + ra;
#pragma unroll
            for (int j = 0; j < 4; j++) {
                int col = ch * 32 + j * 8 + coff;
                float bb0 = __ldg(&bp[col]);
                float bb1 = __ldg(&bp[col + 1]);
                float v0 = acc[j][0] + bb0, v1 = acc[j][1] + bb1;
                float v2 = acc[j][2] + bb0, v3 = acc[j][3] + bb1;
                if (m < 3) {
                    __half* outh = (m == 0) ? g_Kh : (m == 1) ? g_Qh : g_Vh;
                    if (r0g < n)
                        *reinterpret_cast<__half2*>(outh + (size_t)r0g * DF + col) =
                            __floats2half2_rn(v0, v1);
                    if (r0g + 8 < n)
                        *reinterpret_cast<__half2*>(outh + (size_t)(r0g + 8) * DF + col) =
                            __floats2half2_rn(v2, v3);
                } else {
                    if (r0g < n)
                        *reinterpret_cast<float2*>(g_H + (size_t)r0g * DF + col) =
                            make_float2(v0, v1);
                    if (r0g + 8 < n)
                        *reinterpret_cast<float2*>(g_H + (size_t)(r0g + 8) * DF + col) =
                            make_float2(v2, v3);
                }
            }
        }
    }
}

// ---------------- 3: edge gather (fp16) + gate + fp32 vector-atomic scatter --------------
// 8 threads per edge-PAIR: each thread handles features c*8..c*8+7 of TWO
// consecutive edges; 6 gathers issued before any compute (MLP 6). Edge indices
// read directly from the input tensor (int64 or int32 via g_is64).
__global__ void __launch_bounds__(256) edge_kernel(const void* __restrict__ ei, int e) {
    int idx = blockIdx.x * blockDim.x + threadIdx.x;
    int pair = idx >> 3;
    int c = idx & 7;
    int ed0 = pair * 2;
    if (ed0 >= e) return;
    int ed1 = ed0 + 1;
    bool has1 = (ed1 < e);

    int s0, d0, s1, d1;
    if (g_is64) {
        const long long* p = (const long long*)ei;
        s0 = (int)p[ed0]; d0 = (int)p[e + ed0];
        s1 = has1 ? (int)p[ed1] : s0;
        d1 = has1 ? (int)p[e + ed1] : d0;
    } else {
        const int* p = (const int*)ei;
        s0 = p[ed0]; d0 = p[e + ed0];
        s1 = has1 ? p[ed1] : s0;
        d1 = has1 ? p[e + ed1] : d0;
    }

    const uint4* Kp = reinterpret_cast<const uint4*>(g_Kh);
    const uint4* Qp = reinterpret_cast<const uint4*>(g_Qh);
    const uint4* Vp = reinterpret_cast<const uint4*>(g_Vh);
    uint4 kr0 = __ldg(&Kp[(size_t)d0 * 8 + c]);
    uint4 qr0 = __ldg(&Qp[(size_t)s0 * 8 + c]);
    uint4 vr0 = __ldg(&Vp[(size_t)s0 * 8 + c]);
    uint4 kr1 = __ldg(&Kp[(size_t)d1 * 8 + c]);
    uint4 qr1 = __ldg(&Qp[(size_t)s1 * 8 + c]);
    uint4 vr1 = __ldg(&Vp[(size_t)s1 * 8 + c]);

    {
        const __half2* kh = reinterpret_cast<const __half2*>(&kr0);
        const __half2* qh = reinterpret_cast<const __half2*>(&qr0);
        const __half2* vh = reinterpret_cast<const __half2*>(&vr0);
        float msg[8];
#pragma unroll
        for (int p = 0; p < 4; p++) {
            float2 kf = __half22float2(kh[p]);
            float2 qf = __half22float2(qh[p]);
            float2 vf = __half22float2(vh[p]);
            msg[2 * p]     = __fdividef(vf.x, 1.0f + __expf(-(kf.x + qf.x)));
            msg[2 * p + 1] = __fdividef(vf.y, 1.0f + __expf(-(kf.y + qf.y)));
        }
        float4* hp = reinterpret_cast<float4*>(g_H + (size_t)d0 * DF + c * 8);
        atomicAdd(hp,     make_float4(msg[0], msg[1], msg[2], msg[3]));
        atomicAdd(hp + 1, make_float4(msg[4], msg[5], msg[6], msg[7]));
    }
    if (has1) {
        const __half2* kh = reinterpret_cast<const __half2*>(&kr1);
        const __half2* qh = reinterpret_cast<const __half2*>(&qr1);
        const __half2* vh = reinterpret_cast<const __half2*>(&vr1);
        float msg[8];
#pragma unroll
        for (int p = 0; p < 4; p++) {
            float2 kf = __half22float2(kh[p]);
            float2 qf = __half22float2(qh[p]);
            float2 vf = __half22float2(vh[p]);
            msg[2 * p]     = __fdividef(vf.x, 1.0f + __expf(-(kf.x + qf.x)));
            msg[2 * p + 1] = __fdividef(vf.y, 1.0f + __expf(-(kf.y + qf.y)));
        }
        float4* hp = reinterpret_cast<float4*>(g_H + (size_t)d1 * DF + c * 8);
        atomicAdd(hp,     make_float4(msg[0], msg[1], msg[2], msg[3]));
        atomicAdd(hp + 1, make_float4(msg[4], msg[5], msg[6], msg[7]));
    }
}

// ---------------- 4: BatchNorm statistics (per-column sum / sumsq) ----------------
__global__ void __launch_bounds__(256) stats_kernel(int n) {
    __shared__ float ss[256], ss2[256];
    int t = threadIdx.x;
    int col = t & 63;
    int q = t >> 6;  // 0..3
    float s = 0.0f, s2 = 0.0f;
    for (int r = blockIdx.x * 4 + q; r < n; r += gridDim.x * 4) {
        float v = g_H[(size_t)r * DF + col];
        s += v;
        s2 += v * v;
    }
    ss[t] = s; ss2[t] = s2;
    __syncthreads();
    if (t < 64) {
        float ts = ss[t] + ss[t + 64] + ss[t + 128] + ss[t + 192];
        float ts2 = ss2[t] + ss2[t + 64] + ss2[t + 128] + ss2[t + 192];
        atomicAdd(&g_sum[t], ts);
        atomicAdd(&g_sumsq[t], ts2);
    }
}

// ---------------- 5: BN affine + ReLU + residual ----------------
__global__ void __launch_bounds__(256) out_kernel(const float* __restrict__ x,
                                                  const float* __restrict__ gamma,
                                                  const float* __restrict__ beta,
                                                  float* __restrict__ out, int n) {
    __shared__ float sc[64], sh[64];
    int t = threadIdx.x;
    if (t < 64) {
        float invn = 1.0f / (float)n;
        float mean = g_sum[t] * invn;
        float var = g_sumsq[t] * invn - mean * mean;
        float s = gamma[t] * rsqrtf(var + 1e-5f);
        sc[t] = s;
        sh[t] = beta[t] - mean * s;
    }
    __syncthreads();
    const float4* H4 = reinterpret_cast<const float4*>(g_H);
    const float4* X4 = reinterpret_cast<const float4*>(x);
    float4* O4 = reinterpret_cast<float4*>(out);
    int total = n * 16;
    for (int i = blockIdx.x * blockDim.x + t; i < total; i += gridDim.x * blockDim.x) {
        int col = (i & 15) * 4;
        float4 h = H4[i];
        float4 xv = X4[i];
        float4 o;
        o.x = fmaxf(h.x * sc[col + 0] + sh[col + 0], 0.0f) + xv.x;
        o.y = fmaxf(h.y * sc[col + 1] + sh[col + 1], 0.0f) + xv.y;
        o.z = fmaxf(h.z * sc[col + 2] + sh[col + 2], 0.0f) + xv.z;
        o.w = fmaxf(h.w * sc[col + 3] + sh[col + 3], 0.0f) + xv.w;
        O4[i] = o;
    }
}

// ---------------- launch ----------------
extern "C" void kernel_launch(void* const* d_in, const int* in_sizes, int n_in,
                              void* d_out, int out_size) {
    const float* x     = (const float*)d_in[0];
    const void*  ei    = d_in[1];
    const float* Wk    = (const float*)d_in[2];
    const float* bk    = (const float*)d_in[3];
    const float* Wq    = (const float*)d_in[4];
    const float* bq    = (const float*)d_in[5];
    const float* Wv    = (const float*)d_in[6];
    const float* bv    = (const float*)d_in[7];
    const float* Ws    = (const float*)d_in[8];
    const float* bs    = (const float*)d_in[9];
    const float* gamma = (const float*)d_in[10];
    const float* beta  = (const float*)d_in[11];

    int n = in_sizes[0] / DF;
    int e = in_sizes[1] / 2;

    static bool attr_done = false;
    if (!attr_done) {
        cudaFuncSetAttribute(gemm_kernel, cudaFuncAttributeMaxDynamicSharedMemorySize,
                             GEMM_SMEM);
        attr_done = true;
    }

    init_kernel<<<1, 256>>>((const int*)ei, e);
    convw_kernel<<<(4 * DF * DF + 255) / 256, 256>>>(Wk, Wq, Wv, Ws);

    gemm_kernel<<<(n + 127) / 128, 256, GEMM_SMEM>>>(x, bk, bq, bv, bs, n);

    int pairs = (e + 1) / 2;
    edge_kernel<<<(pairs * 8 + 255) / 256, 256>>>(ei, e);
    stats_kernel<<<1024, 256>>>(n);
    out_kernel<<<2048, 256>>>(x, gamma, beta, (float*)d_out, n);
}

// round 14
// speedup vs baseline: 2.4957x; 1.3319x over previous
#include <cuda_runtime.h>
#include <cuda_fp16.h>
#include <cstdint>

#define NMAX 100000
#define EMAX 1600000
#define DF 64

// ---------------- device scratch (no allocations allowed) ----------------
__device__ __half g_Kh[NMAX * DF];
__device__ __half g_Qh[NMAX * DF];
__device__ __half g_Vh[NMAX * DF];
__device__ float  g_H[NMAX * DF];     // fp32 skip from GEMM
__device__ __half g_Agg[NMAX * DF];   // fp16 message accumulator (vector RED target)
__device__ __half g_Wh[4 * DF * DF];  // fp16 weights, [m][c][k] row-major
__device__ float  g_sum[DF];
__device__ float  g_sumsq[DF];
__device__ int    g_is64;

// ---------------- mma helpers ----------------
__device__ __forceinline__ void ldsm_x4(unsigned* r, uint32_t addr) {
    asm volatile("ldmatrix.sync.aligned.m8n8.x4.shared.b16 {%0,%1,%2,%3}, [%4];\n"
                 : "=r"(r[0]), "=r"(r[1]), "=r"(r[2]), "=r"(r[3]) : "r"(addr));
}
__device__ __forceinline__ void mma16816(float* d, const unsigned* a, const unsigned* b) {
    asm volatile(
        "mma.sync.aligned.m16n8k16.row.col.f32.f16.f16.f32 "
        "{%0,%1,%2,%3}, {%4,%5,%6,%7}, {%8,%9}, {%0,%1,%2,%3};\n"
        : "+f"(d[0]), "+f"(d[1]), "+f"(d[2]), "+f"(d[3])
        : "r"(a[0]), "r"(a[1]), "r"(a[2]), "r"(a[3]), "r"(b[0]), "r"(b[1]));
}
// 16B fp16 vector reduction (sm_90+): 8 halves per lane, one instruction.
__device__ __forceinline__ void red_v4f16x2(__half* p, unsigned a0, unsigned a1,
                                            unsigned a2, unsigned a3) {
    asm volatile("red.global.add.noftz.v4.f16x2 [%0], {%1,%2,%3,%4};"
                 :: "l"(p), "r"(a0), "r"(a1), "r"(a2), "r"(a3) : "memory");
}

// ---------------- 0: detect int64-vs-int32 edge_index; zero BN sums ----------------
__global__ void init_kernel(const int* __restrict__ ei32, int e) {
    __shared__ int any;
    int t = threadIdx.x;
    if (t == 0) any = 0;
    if (t < DF) { g_sum[t] = 0.0f; g_sumsq[t] = 0.0f; }
    __syncthreads();
    int nz = 0;
    for (int i = t; i < 1024; i += blockDim.x) {
        if (i < e) nz |= ei32[2 * i + 1];
    }
    if (nz) atomicOr(&any, 1);
    __syncthreads();
    if (t == 0) g_is64 = any ? 0 : 1;
}

// ---------------- 1: zero the fp16 aggregation buffer ----------------
__global__ void zero_agg_kernel(int n) {
    int i = blockIdx.x * blockDim.x + threadIdx.x;
    if (i < n * 8) {   // n*64 halves = n*8 uint4
        uint4 z; z.x = 0; z.y = 0; z.z = 0; z.w = 0;
        reinterpret_cast<uint4*>(g_Agg)[i] = z;
    }
}

// ---------------- 2: weights -> fp16 ----------------
__global__ void convw_kernel(const float* __restrict__ Wk, const float* __restrict__ Wq,
                             const float* __restrict__ Wv, const float* __restrict__ Ws) {
    int idx = blockIdx.x * blockDim.x + threadIdx.x;
    if (idx >= 4 * DF * DF) return;
    int m = idx >> 12;
    int i = idx & 4095;
    const float* W = (m == 0) ? Wk : (m == 1) ? Wq : (m == 2) ? Wv : Ws;
    g_Wh[idx] = __float2half(W[i]);
}

// ---------------- 3: tensor-core GEMM: all 4 matrices, one launch, one sync ------------
// Block: 128 rows staged, two 64-row halves reuse the staged weights. 256 threads;
// warp task per half = 16 rows x 32 cols across all 4 matrices. A-fragments loaded
// once per half, reused for the 4 matrices.
#define GEMM_SMEM ((128 * 72 + 4 * 64 * 72) * 2)

__global__ void __launch_bounds__(256) gemm_kernel(const float* __restrict__ x,
                                                   const float* __restrict__ bk,
                                                   const float* __restrict__ bq,
                                                   const float* __restrict__ bv,
                                                   const float* __restrict__ bs,
                                                   int n) {
    extern __shared__ __half smh[];
    __half* xs = smh;                 // [128][72]
    __half* ws = smh + 128 * 72;      // [4][64][72]
    int t = threadIdx.x;
    int lane = t & 31, w = t >> 5;
    int row0 = blockIdx.x * 128;

    for (int idx = t; idx < 128 * 16; idx += 256) {
        int r = idx >> 4, k4 = idx & 15;
        float4 v = make_float4(0.f, 0.f, 0.f, 0.f);
        if (row0 + r < n)
            v = reinterpret_cast<const float4*>(x + (size_t)(row0 + r) * DF)[k4];
        __half2 h0 = __floats2half2_rn(v.x, v.y);
        __half2 h1 = __floats2half2_rn(v.z, v.w);
        uint2 u;
        u.x = reinterpret_cast<unsigned&>(h0);
        u.y = reinterpret_cast<unsigned&>(h1);
        *reinterpret_cast<uint2*>(&xs[r * 72 + k4 * 4]) = u;
    }
    for (int idx = t; idx < 4 * 64 * 8; idx += 256) {
        int mr = idx >> 3, k8 = idx & 7;
        uint4 v = *reinterpret_cast<const uint4*>(&g_Wh[mr * DF + k8 * 8]);
        *reinterpret_cast<uint4*>(&ws[mr * 72 + k8 * 8]) = v;
    }
    __syncthreads();

    int rt = w >> 1;
    int ch = w & 1;
    int a_row = lane & 15;
    int a_ch  = lane >> 4;
    int b_row = lane & 7;
    int b_ch  = (lane >> 3) & 1;
    int b_nt  = lane >> 4;
    int ra = (lane >> 2);
    int coff = (lane & 3) * 2;

    for (int hh = 0; hh < 2; hh++) {
        int rbase = hh * 64 + rt * 16;

        unsigned a[4][4];
#pragma unroll
        for (int ks = 0; ks < 4; ks++) {
            uint32_t addr = (uint32_t)__cvta_generic_to_shared(
                &xs[(rbase + a_row) * 72 + ks * 16 + a_ch * 8]);
            ldsm_x4(a[ks], addr);
        }

#pragma unroll
        for (int m = 0; m < 4; m++) {
            float acc[4][4];
#pragma unroll
            for (int j = 0; j < 4; j++)
#pragma unroll
                for (int c = 0; c < 4; c++) acc[j][c] = 0.0f;

#pragma unroll
            for (int ks = 0; ks < 4; ks++) {
                unsigned b[4][2];
#pragma unroll
                for (int h = 0; h < 2; h++) {
                    uint32_t addr = (uint32_t)__cvta_generic_to_shared(
                        &ws[(m * 64 + ch * 32 + h * 16 + 8 * b_nt + b_row) * 72 +
                            ks * 16 + b_ch * 8]);
                    unsigned r4[4];
                    ldsm_x4(r4, addr);
                    b[2 * h][0] = r4[0];     b[2 * h][1] = r4[1];
                    b[2 * h + 1][0] = r4[2]; b[2 * h + 1][1] = r4[3];
                }
#pragma unroll
                for (int j = 0; j < 4; j++)
                    mma16816(acc[j], a[ks], b[j]);
            }

            const float* bp = (m == 0) ? bk : (m == 1) ? bq : (m == 2) ? bv : bs;
            int r0g = row0 + rbase + ra;
#pragma unroll
            for (int j = 0; j < 4; j++) {
                int col = ch * 32 + j * 8 + coff;
                float bb0 = __ldg(&bp[col]);
                float bb1 = __ldg(&bp[col + 1]);
                float v0 = acc[j][0] + bb0, v1 = acc[j][1] + bb1;
                float v2 = acc[j][2] + bb0, v3 = acc[j][3] + bb1;
                if (m < 3) {
                    __half* outh = (m == 0) ? g_Kh : (m == 1) ? g_Qh : g_Vh;
                    if (r0g < n)
                        *reinterpret_cast<__half2*>(outh + (size_t)r0g * DF + col) =
                            __floats2half2_rn(v0, v1);
                    if (r0g + 8 < n)
                        *reinterpret_cast<__half2*>(outh + (size_t)(r0g + 8) * DF + col) =
                            __floats2half2_rn(v2, v3);
                } else {
                    if (r0g < n)
                        *reinterpret_cast<float2*>(g_H + (size_t)r0g * DF + col) =
                            make_float2(v0, v1);
                    if (r0g + 8 < n)
                        *reinterpret_cast<float2*>(g_H + (size_t)(r0g + 8) * DF + col) =
                            make_float2(v2, v3);
                }
            }
        }
    }
}

// ---------------- 4: edge gather (fp16) + gate + fp16 VECTOR red scatter --------------
// 8 threads per edge-PAIR: each thread handles features c*8..c*8+7 of TWO
// consecutive edges; 6 gathers issued before any compute. One 16B red.v4.f16x2
// per edge per thread (8 atomic lanes/edge instead of 16 fp32 lanes).
__global__ void __launch_bounds__(256) edge_kernel(const void* __restrict__ ei, int e) {
    int idx = blockIdx.x * blockDim.x + threadIdx.x;
    int pair = idx >> 3;
    int c = idx & 7;
    int ed0 = pair * 2;
    if (ed0 >= e) return;
    int ed1 = ed0 + 1;
    bool has1 = (ed1 < e);

    int s0, d0, s1, d1;
    if (g_is64) {
        const long long* p = (const long long*)ei;
        s0 = (int)p[ed0]; d0 = (int)p[e + ed0];
        s1 = has1 ? (int)p[ed1] : s0;
        d1 = has1 ? (int)p[e + ed1] : d0;
    } else {
        const int* p = (const int*)ei;
        s0 = p[ed0]; d0 = p[e + ed0];
        s1 = has1 ? p[ed1] : s0;
        d1 = has1 ? p[e + ed1] : d0;
    }

    const uint4* Kp = reinterpret_cast<const uint4*>(g_Kh);
    const uint4* Qp = reinterpret_cast<const uint4*>(g_Qh);
    const uint4* Vp = reinterpret_cast<const uint4*>(g_Vh);
    uint4 kr0 = __ldg(&Kp[(size_t)d0 * 8 + c]);
    uint4 qr0 = __ldg(&Qp[(size_t)s0 * 8 + c]);
    uint4 vr0 = __ldg(&Vp[(size_t)s0 * 8 + c]);
    uint4 kr1 = __ldg(&Kp[(size_t)d1 * 8 + c]);
    uint4 qr1 = __ldg(&Qp[(size_t)s1 * 8 + c]);
    uint4 vr1 = __ldg(&Vp[(size_t)s1 * 8 + c]);

    {
        const __half2* kh = reinterpret_cast<const __half2*>(&kr0);
        const __half2* qh = reinterpret_cast<const __half2*>(&qr0);
        const __half2* vh = reinterpret_cast<const __half2*>(&vr0);
        unsigned a[4];
#pragma unroll
        for (int p = 0; p < 4; p++) {
            float2 kf = __half22float2(kh[p]);
            float2 qf = __half22float2(qh[p]);
            float2 vf = __half22float2(vh[p]);
            float m0 = __fdividef(vf.x, 1.0f + __expf(-(kf.x + qf.x)));
            float m1 = __fdividef(vf.y, 1.0f + __expf(-(kf.y + qf.y)));
            __half2 h = __floats2half2_rn(m0, m1);
            a[p] = reinterpret_cast<unsigned&>(h);
        }
        red_v4f16x2(g_Agg + (size_t)d0 * DF + c * 8, a[0], a[1], a[2], a[3]);
    }
    if (has1) {
        const __half2* kh = reinterpret_cast<const __half2*>(&kr1);
        const __half2* qh = reinterpret_cast<const __half2*>(&qr1);
        const __half2* vh = reinterpret_cast<const __half2*>(&vr1);
        unsigned a[4];
#pragma unroll
        for (int p = 0; p < 4; p++) {
            float2 kf = __half22float2(kh[p]);
            float2 qf = __half22float2(qh[p]);
            float2 vf = __half22float2(vh[p]);
            float m0 = __fdividef(vf.x, 1.0f + __expf(-(kf.x + qf.x)));
            float m1 = __fdividef(vf.y, 1.0f + __expf(-(kf.y + qf.y)));
            __half2 h = __floats2half2_rn(m0, m1);
            a[p] = reinterpret_cast<unsigned&>(h);
        }
        red_v4f16x2(g_Agg + (size_t)d1 * DF + c * 8, a[0], a[1], a[2], a[3]);
    }
}

// ---------------- 5: BatchNorm statistics (h = skip + agg) ----------------
__global__ void __launch_bounds__(256) stats_kernel(int n) {
    __shared__ float ss[256], ss2[256];
    int t = threadIdx.x;
    int col = t & 63;
    int q = t >> 6;  // 0..3
    float s = 0.0f, s2 = 0.0f;
    for (int r = blockIdx.x * 4 + q; r < n; r += gridDim.x * 4) {
        size_t idx = (size_t)r * DF + col;
        float v = g_H[idx] + __half2float(g_Agg[idx]);
        s += v;
        s2 += v * v;
    }
    ss[t] = s; ss2[t] = s2;
    __syncthreads();
    if (t < 64) {
        float ts = ss[t] + ss[t + 64] + ss[t + 128] + ss[t + 192];
        float ts2 = ss2[t] + ss2[t + 64] + ss2[t + 128] + ss2[t + 192];
        atomicAdd(&g_sum[t], ts);
        atomicAdd(&g_sumsq[t], ts2);
    }
}

// ---------------- 6: BN affine + ReLU + residual ----------------
__global__ void __launch_bounds__(256) out_kernel(const float* __restrict__ x,
                                                  const float* __restrict__ gamma,
                                                  const float* __restrict__ beta,
                                                  float* __restrict__ out, int n) {
    __shared__ float sc[64], sh[64];
    int t = threadIdx.x;
    if (t < 64) {
        float invn = 1.0f / (float)n;
        float mean = g_sum[t] * invn;
        float var = g_sumsq[t] * invn - mean * mean;
        float s = gamma[t] * rsqrtf(var + 1e-5f);
        sc[t] = s;
        sh[t] = beta[t] - mean * s;
    }
    __syncthreads();
    const float4* H4 = reinterpret_cast<const float4*>(g_H);
    const uint2* A2 = reinterpret_cast<const uint2*>(g_Agg);
    const float4* X4 = reinterpret_cast<const float4*>(x);
    float4* O4 = reinterpret_cast<float4*>(out);
    int total = n * 16;
    for (int i = blockIdx.x * blockDim.x + t; i < total; i += gridDim.x * blockDim.x) {
        int col = (i & 15) * 4;
        float4 h = H4[i];
        uint2 au = A2[i];
        __half2 al = reinterpret_cast<__half2&>(au.x);
        __half2 ah = reinterpret_cast<__half2&>(au.y);
        float2 a01 = __half22float2(al);
        float2 a23 = __half22float2(ah);
        h.x += a01.x; h.y += a01.y; h.z += a23.x; h.w += a23.y;
        float4 xv = X4[i];
        float4 o;
        o.x = fmaxf(h.x * sc[col + 0] + sh[col + 0], 0.0f) + xv.x;
        o.y = fmaxf(h.y * sc[col + 1] + sh[col + 1], 0.0f) + xv.y;
        o.z = fmaxf(h.z * sc[col + 2] + sh[col + 2], 0.0f) + xv.z;
        o.w = fmaxf(h.w * sc[col + 3] + sh[col + 3], 0.0f) + xv.w;
        O4[i] = o;
    }
}

// ---------------- launch ----------------
extern "C" void kernel_launch(void* const* d_in, const int* in_sizes, int n_in,
                              void* d_out, int out_size) {
    const float* x     = (const float*)d_in[0];
    const void*  ei    = d_in[1];
    const float* Wk    = (const float*)d_in[2];
    const float* bk    = (const float*)d_in[3];
    const float* Wq    = (const float*)d_in[4];
    const float* bq    = (const float*)d_in[5];
    const float* Wv    = (const float*)d_in[6];
    const float* bv    = (const float*)d_in[7];
    const float* Ws    = (const float*)d_in[8];
    const float* bs    = (const float*)d_in[9];
    const float* gamma = (const float*)d_in[10];
    const float* beta  = (const float*)d_in[11];

    int n = in_sizes[0] / DF;
    int e = in_sizes[1] / 2;

    static bool attr_done = false;
    if (!attr_done) {
        cudaFuncSetAttribute(gemm_kernel, cudaFuncAttributeMaxDynamicSharedMemorySize,
                             GEMM_SMEM);
        attr_done = true;
    }

    init_kernel<<<1, 256>>>((const int*)ei, e);
    zero_agg_kernel<<<(n * 8 + 255) / 256, 256>>>(n);
    convw_kernel<<<(4 * DF * DF + 255) / 256, 256>>>(Wk, Wq, Wv, Ws);

    gemm_kernel<<<(n + 127) / 128, 256, GEMM_SMEM>>>(x, bk, bq, bv, bs, n);

    int pairs = (e + 1) / 2;
    edge_kernel<<<(pairs * 8 + 255) / 256, 256>>>(ei, e);
    stats_kernel<<<1024, 256>>>(n);
    out_kernel<<<2048, 256>>>(x, gamma, beta, (float*)d_out, n);
}

// round 15
// speedup vs baseline: 2.7810x; 1.1143x over previous
#include <cuda_runtime.h>
#include <cuda_fp16.h>
#include <cstdint>

#define NMAX 100000
#define EMAX 1600000
#define DF 64

// ---------------- device scratch (no allocations allowed) ----------------
__device__ __half g_Kh[NMAX * DF];
__device__ __half g_Qh[NMAX * DF];
__device__ __half g_Vh[NMAX * DF];
__device__ __half g_Agg[NMAX * DF];   // fp16: skip (from GEMM) + messages (RED target)
__device__ __half g_Wh[4 * DF * DF];  // fp16 weights, [m][c][k] row-major
__device__ float  g_sum[DF];
__device__ float  g_sumsq[DF];
__device__ int    g_is64;

// ---------------- mma helpers ----------------
__device__ __forceinline__ void ldsm_x4(unsigned* r, uint32_t addr) {
    asm volatile("ldmatrix.sync.aligned.m8n8.x4.shared.b16 {%0,%1,%2,%3}, [%4];\n"
                 : "=r"(r[0]), "=r"(r[1]), "=r"(r[2]), "=r"(r[3]) : "r"(addr));
}
__device__ __forceinline__ void mma16816(float* d, const unsigned* a, const unsigned* b) {
    asm volatile(
        "mma.sync.aligned.m16n8k16.row.col.f32.f16.f16.f32 "
        "{%0,%1,%2,%3}, {%4,%5,%6,%7}, {%8,%9}, {%0,%1,%2,%3};\n"
        : "+f"(d[0]), "+f"(d[1]), "+f"(d[2]), "+f"(d[3])
        : "r"(a[0]), "r"(a[1]), "r"(a[2]), "r"(a[3]), "r"(b[0]), "r"(b[1]));
}
// 16B fp16 vector reduction (sm_90+): 8 halves per lane, one instruction.
__device__ __forceinline__ void red_v4f16x2(__half* p, unsigned a0, unsigned a1,
                                            unsigned a2, unsigned a3) {
    asm volatile("red.global.add.noftz.v4.f16x2 [%0], {%1,%2,%3,%4};"
                 :: "l"(p), "r"(a0), "r"(a1), "r"(a2), "r"(a3) : "memory");
}

// ---------------- 0: prep — zero BN sums, detect index width, weights -> fp16 ----------
__global__ void prep_kernel(const int* __restrict__ ei32, int e,
                            const float* __restrict__ Wk, const float* __restrict__ Wq,
                            const float* __restrict__ Wv, const float* __restrict__ Ws) {
    int gt = blockIdx.x * blockDim.x + threadIdx.x;
    if (gt < DF) { g_sum[gt] = 0.0f; g_sumsq[gt] = 0.0f; }
    if (gt < 4 * DF * DF) {
        int m = gt >> 12;
        int i = gt & 4095;
        const float* W = (m == 0) ? Wk : (m == 1) ? Wq : (m == 2) ? Wv : Ws;
        g_Wh[gt] = __float2half(W[i]);
    }
    if (blockIdx.x == 0) {
        __shared__ int any;
        int t = threadIdx.x;
        if (t == 0) any = 0;
        __syncthreads();
        int nz = 0;
        for (int i = t; i < 1024; i += blockDim.x)
            if (i < e) nz |= ei32[2 * i + 1];
        if (nz) atomicOr(&any, 1);
        __syncthreads();
        if (t == 0) g_is64 = any ? 0 : 1;
    }
}

// ---------------- 1: tensor-core GEMM: all 4 matrices, one launch, one sync ------------
// Block: 64 rows, 256 threads (8 warps). Warp task = 16 rows x 32 cols across all
// 4 matrices (rt = w>>1, ch = w&1). A-fragments loaded once, reused for 4 matrices.
// All outputs fp16 (m=3 -> g_Agg seeds the skip for the fp16 RED accumulator).
#define GEMM_SMEM ((64 * 72 + 4 * 64 * 72) * 2)

__global__ void __launch_bounds__(256) gemm_kernel(const float* __restrict__ x,
                                                   const float* __restrict__ bk,
                                                   const float* __restrict__ bq,
                                                   const float* __restrict__ bv,
                                                   const float* __restrict__ bs,
                                                   int n) {
    extern __shared__ __half smh[];
    __half* xs = smh;                 // [64][72]
    __half* ws = smh + 64 * 72;       // [4][64][72]
    int t = threadIdx.x;
    int lane = t & 31, w = t >> 5;
    int row0 = blockIdx.x * 64;

    // Stage x -> fp16 (zero-fill OOB rows)
    for (int idx = t; idx < 64 * 16; idx += 256) {
        int r = idx >> 4, k4 = idx & 15;
        float4 v = make_float4(0.f, 0.f, 0.f, 0.f);
        if (row0 + r < n)
            v = reinterpret_cast<const float4*>(x + (size_t)(row0 + r) * DF)[k4];
        __half2 h0 = __floats2half2_rn(v.x, v.y);
        __half2 h1 = __floats2half2_rn(v.z, v.w);
        uint2 u;
        u.x = reinterpret_cast<unsigned&>(h0);
        u.y = reinterpret_cast<unsigned&>(h1);
        *reinterpret_cast<uint2*>(&xs[r * 72 + k4 * 4]) = u;
    }
    // Stage all 4 weight matrices
    for (int idx = t; idx < 4 * 64 * 8; idx += 256) {
        int mr = idx >> 3, k8 = idx & 7;
        uint4 v = *reinterpret_cast<const uint4*>(&g_Wh[mr * DF + k8 * 8]);
        *reinterpret_cast<uint4*>(&ws[mr * 72 + k8 * 8]) = v;
    }
    __syncthreads();

    int rt = w >> 1;          // row-group 0..3 (16 rows each)
    int ch = w & 1;           // col-half 0..1 (32 cols each)
    int a_row = lane & 15;
    int a_ch  = lane >> 4;
    int b_row = lane & 7;
    int b_ch  = (lane >> 3) & 1;
    int b_nt  = lane >> 4;

    // A fragments: 1 m16 tile x 4 ks, loaded once, reused for all 4 matrices
    unsigned a[4][4];
#pragma unroll
    for (int ks = 0; ks < 4; ks++) {
        uint32_t addr = (uint32_t)__cvta_generic_to_shared(
            &xs[(rt * 16 + a_row) * 72 + ks * 16 + a_ch * 8]);
        ldsm_x4(a[ks], addr);
    }

    int ra = (lane >> 2);
    int coff = (lane & 3) * 2;

#pragma unroll
    for (int m = 0; m < 4; m++) {
        float acc[4][4];
#pragma unroll
        for (int j = 0; j < 4; j++)
#pragma unroll
            for (int c = 0; c < 4; c++) acc[j][c] = 0.0f;

#pragma unroll
        for (int ks = 0; ks < 4; ks++) {
            unsigned b[4][2];
#pragma unroll
            for (int h = 0; h < 2; h++) {
                uint32_t addr = (uint32_t)__cvta_generic_to_shared(
                    &ws[(m * 64 + ch * 32 + h * 16 + 8 * b_nt + b_row) * 72 +
                        ks * 16 + b_ch * 8]);
                unsigned r4[4];
                ldsm_x4(r4, addr);
                b[2 * h][0] = r4[0];     b[2 * h][1] = r4[1];
                b[2 * h + 1][0] = r4[2]; b[2 * h + 1][1] = r4[3];
            }
#pragma unroll
            for (int j = 0; j < 4; j++)
                mma16816(acc[j], a[ks], b[j]);
        }

        const float* bp = (m == 0) ? bk : (m == 1) ? bq : (m == 2) ? bv : bs;
        __half* outh = (m == 0) ? g_Kh : (m == 1) ? g_Qh : (m == 2) ? g_Vh : g_Agg;
        int r0g = row0 + rt * 16 + ra;
#pragma unroll
        for (int j = 0; j < 4; j++) {
            int col = ch * 32 + j * 8 + coff;
            float bb0 = __ldg(&bp[col]);
            float bb1 = __ldg(&bp[col + 1]);
            float v0 = acc[j][0] + bb0, v1 = acc[j][1] + bb1;
            float v2 = acc[j][2] + bb0, v3 = acc[j][3] + bb1;
            if (r0g < n)
                *reinterpret_cast<__half2*>(outh + (size_t)r0g * DF + col) =
                    __floats2half2_rn(v0, v1);
            if (r0g + 8 < n)
                *reinterpret_cast<__half2*>(outh + (size_t)(r0g + 8) * DF + col) =
                    __floats2half2_rn(v2, v3);
        }
    }
}

// ---------------- 2: edge gather (fp16) + gate + fp16 VECTOR red scatter --------------
// 8 threads per edge-PAIR: each thread handles features c*8..c*8+7 of TWO
// consecutive edges; 6 gathers issued before any compute. One 16B red.v4.f16x2
// per edge per thread into g_Agg (which already holds the skip).
__global__ void __launch_bounds__(256) edge_kernel(const void* __restrict__ ei, int e) {
    int idx = blockIdx.x * blockDim.x + threadIdx.x;
    int pair = idx >> 3;
    int c = idx & 7;
    int ed0 = pair * 2;
    if (ed0 >= e) return;
    int ed1 = ed0 + 1;
    bool has1 = (ed1 < e);

    int s0, d0, s1, d1;
    if (g_is64) {
        const long long* p = (const long long*)ei;
        s0 = (int)p[ed0]; d0 = (int)p[e + ed0];
        s1 = has1 ? (int)p[ed1] : s0;
        d1 = has1 ? (int)p[e + ed1] : d0;
    } else {
        const int* p = (const int*)ei;
        s0 = p[ed0]; d0 = p[e + ed0];
        s1 = has1 ? p[ed1] : s0;
        d1 = has1 ? p[e + ed1] : d0;
    }

    const uint4* Kp = reinterpret_cast<const uint4*>(g_Kh);
    const uint4* Qp = reinterpret_cast<const uint4*>(g_Qh);
    const uint4* Vp = reinterpret_cast<const uint4*>(g_Vh);
    uint4 kr0 = __ldg(&Kp[(size_t)d0 * 8 + c]);
    uint4 qr0 = __ldg(&Qp[(size_t)s0 * 8 + c]);
    uint4 vr0 = __ldg(&Vp[(size_t)s0 * 8 + c]);
    uint4 kr1 = __ldg(&Kp[(size_t)d1 * 8 + c]);
    uint4 qr1 = __ldg(&Qp[(size_t)s1 * 8 + c]);
    uint4 vr1 = __ldg(&Vp[(size_t)s1 * 8 + c]);

    {
        const __half2* kh = reinterpret_cast<const __half2*>(&kr0);
        const __half2* qh = reinterpret_cast<const __half2*>(&qr0);
        const __half2* vh = reinterpret_cast<const __half2*>(&vr0);
        unsigned a[4];
#pragma unroll
        for (int p = 0; p < 4; p++) {
            float2 kf = __half22float2(kh[p]);
            float2 qf = __half22float2(qh[p]);
            float2 vf = __half22float2(vh[p]);
            float m0 = __fdividef(vf.x, 1.0f + __expf(-(kf.x + qf.x)));
            float m1 = __fdividef(vf.y, 1.0f + __expf(-(kf.y + qf.y)));
            __half2 h = __floats2half2_rn(m0, m1);
            a[p] = reinterpret_cast<unsigned&>(h);
        }
        red_v4f16x2(g_Agg + (size_t)d0 * DF + c * 8, a[0], a[1], a[2], a[3]);
    }
    if (has1) {
        const __half2* kh = reinterpret_cast<const __half2*>(&kr1);
        const __half2* qh = reinterpret_cast<const __half2*>(&qr1);
        const __half2* vh = reinterpret_cast<const __half2*>(&vr1);
        unsigned a[4];
#pragma unroll
        for (int p = 0; p < 4; p++) {
            float2 kf = __half22float2(kh[p]);
            float2 qf = __half22float2(qh[p]);
            float2 vf = __half22float2(vh[p]);
            float m0 = __fdividef(vf.x, 1.0f + __expf(-(kf.x + qf.x)));
            float m1 = __fdividef(vf.y, 1.0f + __expf(-(kf.y + qf.y)));
            __half2 h = __floats2half2_rn(m0, m1);
            a[p] = reinterpret_cast<unsigned&>(h);
        }
        red_v4f16x2(g_Agg + (size_t)d1 * DF + c * 8, a[0], a[1], a[2], a[3]);
    }
}

// ---------------- 3: BatchNorm statistics (h = g_Agg, fp16) ----------------
__global__ void __launch_bounds__(256) stats_kernel(int n) {
    __shared__ float ss[256], ss2[256];
    int t = threadIdx.x;
    int col = t & 63;
    int q = t >> 6;  // 0..3
    float s = 0.0f, s2 = 0.0f;
    for (int r = blockIdx.x * 4 + q; r < n; r += gridDim.x * 4) {
        float v = __half2float(g_Agg[(size_t)r * DF + col]);
        s += v;
        s2 += v * v;
    }
    ss[t] = s; ss2[t] = s2;
    __syncthreads();
    if (t < 64) {
        float ts = ss[t] + ss[t + 64] + ss[t + 128] + ss[t + 192];
        float ts2 = ss2[t] + ss2[t + 64] + ss2[t + 128] + ss2[t + 192];
        atomicAdd(&g_sum[t], ts);
        atomicAdd(&g_sumsq[t], ts2);
    }
}

// ---------------- 4: BN affine + ReLU + residual ----------------
__global__ void __launch_bounds__(256) out_kernel(const float* __restrict__ x,
                                                  const float* __restrict__ gamma,
                                                  const float* __restrict__ beta,
                                                  float* __restrict__ out, int n) {
    __shared__ float sc[64], sh[64];
    int t = threadIdx.x;
    if (t < 64) {
        float invn = 1.0f / (float)n;
        float mean = g_sum[t] * invn;
        float var = g_sumsq[t] * invn - mean * mean;
        float s = gamma[t] * rsqrtf(var + 1e-5f);
        sc[t] = s;
        sh[t] = beta[t] - mean * s;
    }
    __syncthreads();
    const uint2* A2 = reinterpret_cast<const uint2*>(g_Agg);
    const float4* X4 = reinterpret_cast<const float4*>(x);
    float4* O4 = reinterpret_cast<float4*>(out);
    int total = n * 16;
    for (int i = blockIdx.x * blockDim.x + t; i < total; i += gridDim.x * blockDim.x) {
        int col = (i & 15) * 4;
        uint2 au = A2[i];
        __half2 al = reinterpret_cast<__half2&>(au.x);
        __half2 ah = reinterpret_cast<__half2&>(au.y);
        float2 a01 = __half22float2(al);
        float2 a23 = __half22float2(ah);
        float4 xv = X4[i];
        float4 o;
        o.x = fmaxf(a01.x * sc[col + 0] + sh[col + 0], 0.0f) + xv.x;
        o.y = fmaxf(a01.y * sc[col + 1] + sh[col + 1], 0.0f) + xv.y;
        o.z = fmaxf(a23.x * sc[col + 2] + sh[col + 2], 0.0f) + xv.z;
        o.w = fmaxf(a23.y * sc[col + 3] + sh[col + 3], 0.0f) + xv.w;
        O4[i] = o;
    }
}

// ---------------- launch ----------------
extern "C" void kernel_launch(void* const* d_in, const int* in_sizes, int n_in,
                              void* d_out, int out_size) {
    const float* x     = (const float*)d_in[0];
    const void*  ei    = d_in[1];
    const float* Wk    = (const float*)d_in[2];
    const float* bk    = (const float*)d_in[3];
    const float* Wq    = (const float*)d_in[4];
    const float* bq    = (const float*)d_in[5];
    const float* Wv    = (const float*)d_in[6];
    const float* bv    = (const float*)d_in[7];
    const float* Ws    = (const float*)d_in[8];
    const float* bs    = (const float*)d_in[9];
    const float* gamma = (const float*)d_in[10];
    const float* beta  = (const float*)d_in[11];

    int n = in_sizes[0] / DF;
    int e = in_sizes[1] / 2;

    static bool attr_done = false;
    if (!attr_done) {
        cudaFuncSetAttribute(gemm_kernel, cudaFuncAttributeMaxDynamicSharedMemorySize,
                             GEMM_SMEM);
        attr_done = true;
    }

    prep_kernel<<<64, 256>>>((const int*)ei, e, Wk, Wq, Wv, Ws);

    gemm_kernel<<<(n + 63) / 64, 256, GEMM_SMEM>>>(x, bk, bq, bv, bs, n);

    int pairs = (e + 1) / 2;
    edge_kernel<<<(pairs * 8 + 255) / 256, 256>>>(ei, e);
    stats_kernel<<<1024, 256>>>(n);
    out_kernel<<<2048, 256>>>(x, gamma, beta, (float*)d_out, n);
}

// round 16
// speedup vs baseline: 2.9130x; 1.0475x over previous
#include <cuda_runtime.h>
#include <cuda_fp16.h>
#include <cstdint>

#define NMAX 100000
#define EMAX 1600000
#define DF 64

// ---------------- device scratch (no allocations allowed) ----------------
__device__ __half g_Kh[NMAX * DF];
__device__ __half g_Qh[NMAX * DF];
__device__ __half g_Vh[NMAX * DF];
__device__ __half g_Agg[NMAX * DF];   // fp16: skip (from GEMM) + messages (RED target)
__device__ __half g_Wh[4 * DF * DF];  // fp16 weights, [m][c][k] row-major
__device__ float  g_sum[DF];
__device__ float  g_sumsq[DF];
__device__ int    g_is64;

// ---------------- mma helpers ----------------
__device__ __forceinline__ void ldsm_x4(unsigned* r, uint32_t addr) {
    asm volatile("ldmatrix.sync.aligned.m8n8.x4.shared.b16 {%0,%1,%2,%3}, [%4];\n"
                 : "=r"(r[0]), "=r"(r[1]), "=r"(r[2]), "=r"(r[3]) : "r"(addr));
}
__device__ __forceinline__ void mma16816(float* d, const unsigned* a, const unsigned* b) {
    asm volatile(
        "mma.sync.aligned.m16n8k16.row.col.f32.f16.f16.f32 "
        "{%0,%1,%2,%3}, {%4,%5,%6,%7}, {%8,%9}, {%0,%1,%2,%3};\n"
        : "+f"(d[0]), "+f"(d[1]), "+f"(d[2]), "+f"(d[3])
        : "r"(a[0]), "r"(a[1]), "r"(a[2]), "r"(a[3]), "r"(b[0]), "r"(b[1]));
}
// 16B fp16 vector reduction (sm_90+): 8 halves per lane, one instruction.
__device__ __forceinline__ void red_v4f16x2(__half* p, unsigned a0, unsigned a1,
                                            unsigned a2, unsigned a3) {
    asm volatile("red.global.add.noftz.v4.f16x2 [%0], {%1,%2,%3,%4};"
                 :: "l"(p), "r"(a0), "r"(a1), "r"(a2), "r"(a3) : "memory");
}

// ---------------- 0: prep — zero BN sums, detect index width, weights -> fp16 ----------
__global__ void prep_kernel(const int* __restrict__ ei32, int e,
                            const float* __restrict__ Wk, const float* __restrict__ Wq,
                            const float* __restrict__ Wv, const float* __restrict__ Ws) {
    int gt = blockIdx.x * blockDim.x + threadIdx.x;
    if (gt < DF) { g_sum[gt] = 0.0f; g_sumsq[gt] = 0.0f; }
    if (gt < 4 * DF * DF) {
        int m = gt >> 12;
        int i = gt & 4095;
        const float* W = (m == 0) ? Wk : (m == 1) ? Wq : (m == 2) ? Wv : Ws;
        g_Wh[gt] = __float2half(W[i]);
    }
    if (blockIdx.x == 0) {
        __shared__ int any;
        int t = threadIdx.x;
        if (t == 0) any = 0;
        __syncthreads();
        int nz = 0;
        for (int i = t; i < 1024; i += blockDim.x)
            if (i < e) nz |= ei32[2 * i + 1];
        if (nz) atomicOr(&any, 1);
        __syncthreads();
        if (t == 0) g_is64 = any ? 0 : 1;
    }
}

// ---------------- 1: tensor-core GEMM: all 4 matrices, one launch, one sync ------------
// Block: 64 rows, 256 threads (8 warps). Warp task = 16 rows x 32 cols across all
// 4 matrices (rt = w>>1, ch = w&1). A-fragments loaded once, reused for 4 matrices.
// All outputs fp16 (m=3 -> g_Agg seeds the skip for the fp16 RED accumulator).
#define GEMM_SMEM ((64 * 72 + 4 * 64 * 72) * 2)

__global__ void __launch_bounds__(256) gemm_kernel(const float* __restrict__ x,
                                                   const float* __restrict__ bk,
                                                   const float* __restrict__ bq,
                                                   const float* __restrict__ bv,
                                                   const float* __restrict__ bs,
                                                   int n) {
    extern __shared__ __half smh[];
    __half* xs = smh;                 // [64][72]
    __half* ws = smh + 64 * 72;       // [4][64][72]
    int t = threadIdx.x;
    int lane = t & 31, w = t >> 5;
    int row0 = blockIdx.x * 64;

    // Stage x -> fp16 (zero-fill OOB rows)
    for (int idx = t; idx < 64 * 16; idx += 256) {
        int r = idx >> 4, k4 = idx & 15;
        float4 v = make_float4(0.f, 0.f, 0.f, 0.f);
        if (row0 + r < n)
            v = reinterpret_cast<const float4*>(x + (size_t)(row0 + r) * DF)[k4];
        __half2 h0 = __floats2half2_rn(v.x, v.y);
        __half2 h1 = __floats2half2_rn(v.z, v.w);
        uint2 u;
        u.x = reinterpret_cast<unsigned&>(h0);
        u.y = reinterpret_cast<unsigned&>(h1);
        *reinterpret_cast<uint2*>(&xs[r * 72 + k4 * 4]) = u;
    }
    // Stage all 4 weight matrices
    for (int idx = t; idx < 4 * 64 * 8; idx += 256) {
        int mr = idx >> 3, k8 = idx & 7;
        uint4 v = *reinterpret_cast<const uint4*>(&g_Wh[mr * DF + k8 * 8]);
        *reinterpret_cast<uint4*>(&ws[mr * 72 + k8 * 8]) = v;
    }
    __syncthreads();

    int rt = w >> 1;          // row-group 0..3 (16 rows each)
    int ch = w & 1;           // col-half 0..1 (32 cols each)
    int a_row = lane & 15;
    int a_ch  = lane >> 4;
    int b_row = lane & 7;
    int b_ch  = (lane >> 3) & 1;
    int b_nt  = lane >> 4;

    // A fragments: 1 m16 tile x 4 ks, loaded once, reused for all 4 matrices
    unsigned a[4][4];
#pragma unroll
    for (int ks = 0; ks < 4; ks++) {
        uint32_t addr = (uint32_t)__cvta_generic_to_shared(
            &xs[(rt * 16 + a_row) * 72 + ks * 16 + a_ch * 8]);
        ldsm_x4(a[ks], addr);
    }

    int ra = (lane >> 2);
    int coff = (lane & 3) * 2;

#pragma unroll
    for (int m = 0; m < 4; m++) {
        float acc[4][4];
#pragma unroll
        for (int j = 0; j < 4; j++)
#pragma unroll
            for (int c = 0; c < 4; c++) acc[j][c] = 0.0f;

#pragma unroll
        for (int ks = 0; ks < 4; ks++) {
            unsigned b[4][2];
#pragma unroll
            for (int h = 0; h < 2; h++) {
                uint32_t addr = (uint32_t)__cvta_generic_to_shared(
                    &ws[(m * 64 + ch * 32 + h * 16 + 8 * b_nt + b_row) * 72 +
                        ks * 16 + b_ch * 8]);
                unsigned r4[4];
                ldsm_x4(r4, addr);
                b[2 * h][0] = r4[0];     b[2 * h][1] = r4[1];
                b[2 * h + 1][0] = r4[2]; b[2 * h + 1][1] = r4[3];
            }
#pragma unroll
            for (int j = 0; j < 4; j++)
                mma16816(acc[j], a[ks], b[j]);
        }

        const float* bp = (m == 0) ? bk : (m == 1) ? bq : (m == 2) ? bv : bs;
        __half* outh = (m == 0) ? g_Kh : (m == 1) ? g_Qh : (m == 2) ? g_Vh : g_Agg;
        int r0g = row0 + rt * 16 + ra;
#pragma unroll
        for (int j = 0; j < 4; j++) {
            int col = ch * 32 + j * 8 + coff;
            float bb0 = __ldg(&bp[col]);
            float bb1 = __ldg(&bp[col + 1]);
            float v0 = acc[j][0] + bb0, v1 = acc[j][1] + bb1;
            float v2 = acc[j][2] + bb0, v3 = acc[j][3] + bb1;
            if (r0g < n)
                *reinterpret_cast<__half2*>(outh + (size_t)r0g * DF + col) =
                    __floats2half2_rn(v0, v1);
            if (r0g + 8 < n)
                *reinterpret_cast<__half2*>(outh + (size_t)(r0g + 8) * DF + col) =
                    __floats2half2_rn(v2, v3);
        }
    }
}

// ---------------- 2: edge gather (fp16) + gate + fp16 VECTOR red scatter --------------
// 8 threads per edge-PAIR: each thread handles features c*8..c*8+7 of TWO
// consecutive edges; 6 gathers issued before any compute. One 16B red.v4.f16x2
// per edge per thread into g_Agg (which already holds the skip).
__global__ void __launch_bounds__(256) edge_kernel(const void* __restrict__ ei, int e) {
    int idx = blockIdx.x * blockDim.x + threadIdx.x;
    int pair = idx >> 3;
    int c = idx & 7;
    int ed0 = pair * 2;
    if (ed0 >= e) return;
    int ed1 = ed0 + 1;
    bool has1 = (ed1 < e);

    int s0, d0, s1, d1;
    if (g_is64) {
        const long long* p = (const long long*)ei;
        s0 = (int)p[ed0]; d0 = (int)p[e + ed0];
        s1 = has1 ? (int)p[ed1] : s0;
        d1 = has1 ? (int)p[e + ed1] : d0;
    } else {
        const int* p = (const int*)ei;
        s0 = p[ed0]; d0 = p[e + ed0];
        s1 = has1 ? p[ed1] : s0;
        d1 = has1 ? p[e + ed1] : d0;
    }

    const uint4* Kp = reinterpret_cast<const uint4*>(g_Kh);
    const uint4* Qp = reinterpret_cast<const uint4*>(g_Qh);
    const uint4* Vp = reinterpret_cast<const uint4*>(g_Vh);
    uint4 kr0 = __ldg(&Kp[(size_t)d0 * 8 + c]);
    uint4 qr0 = __ldg(&Qp[(size_t)s0 * 8 + c]);
    uint4 vr0 = __ldg(&Vp[(size_t)s0 * 8 + c]);
    uint4 kr1 = __ldg(&Kp[(size_t)d1 * 8 + c]);
    uint4 qr1 = __ldg(&Qp[(size_t)s1 * 8 + c]);
    uint4 vr1 = __ldg(&Vp[(size_t)s1 * 8 + c]);

    {
        const __half2* kh = reinterpret_cast<const __half2*>(&kr0);
        const __half2* qh = reinterpret_cast<const __half2*>(&qr0);
        const __half2* vh = reinterpret_cast<const __half2*>(&vr0);
        unsigned a[4];
#pragma unroll
        for (int p = 0; p < 4; p++) {
            float2 kf = __half22float2(kh[p]);
            float2 qf = __half22float2(qh[p]);
            float2 vf = __half22float2(vh[p]);
            float m0 = __fdividef(vf.x, 1.0f + __expf(-(kf.x + qf.x)));
            float m1 = __fdividef(vf.y, 1.0f + __expf(-(kf.y + qf.y)));
            __half2 h = __floats2half2_rn(m0, m1);
            a[p] = reinterpret_cast<unsigned&>(h);
        }
        red_v4f16x2(g_Agg + (size_t)d0 * DF + c * 8, a[0], a[1], a[2], a[3]);
    }
    if (has1) {
        const __half2* kh = reinterpret_cast<const __half2*>(&kr1);
        const __half2* qh = reinterpret_cast<const __half2*>(&qr1);
        const __half2* vh = reinterpret_cast<const __half2*>(&vr1);
        unsigned a[4];
#pragma unroll
        for (int p = 0; p < 4; p++) {
            float2 kf = __half22float2(kh[p]);
            float2 qf = __half22float2(qh[p]);
            float2 vf = __half22float2(vh[p]);
            float m0 = __fdividef(vf.x, 1.0f + __expf(-(kf.x + qf.x)));
            float m1 = __fdividef(vf.y, 1.0f + __expf(-(kf.y + qf.y)));
            __half2 h = __floats2half2_rn(m0, m1);
            a[p] = reinterpret_cast<unsigned&>(h);
        }
        red_v4f16x2(g_Agg + (size_t)d1 * DF + c * 8, a[0], a[1], a[2], a[3]);
    }
}

// ---------------- 3: BatchNorm statistics — vectorized 16B loads ----------------
// Thread: cg = t&7 owns cols cg*8..cg*8+7 (one uint4 = 8 halves per row);
// row = blockIdx.x*32 + t>>3, stride gridDim.x*32. Warp-reduce the 4 rows that
// share a cg (shfl down 16, 8), then lanes 0..7 atomically add 8 cols each to
// smem; one global atomic per column per block.
__global__ void __launch_bounds__(256) stats_kernel(int n) {
    __shared__ float s_sum[64], s_sq[64];
    int t = threadIdx.x;
    if (t < 64) { s_sum[t] = 0.0f; s_sq[t] = 0.0f; }
    __syncthreads();

    int cg = t & 7;
    int rowoff = t >> 3;   // 0..31
    float s[8], s2[8];
#pragma unroll
    for (int j = 0; j < 8; j++) { s[j] = 0.0f; s2[j] = 0.0f; }

    for (int r = blockIdx.x * 32 + rowoff; r < n; r += gridDim.x * 32) {
        uint4 v = *(reinterpret_cast<const uint4*>(g_Agg) + (size_t)r * 8 + cg);
        const __half2* h = reinterpret_cast<const __half2*>(&v);
#pragma unroll
        for (int p = 0; p < 4; p++) {
            float2 f = __half22float2(h[p]);
            s[2 * p] += f.x;      s2[2 * p] += f.x * f.x;
            s[2 * p + 1] += f.y;  s2[2 * p + 1] += f.y * f.y;
        }
    }
    // Reduce across the 4 lanes in this warp sharing cg (lanes cg, cg+8, cg+16, cg+24)
#pragma unroll
    for (int j = 0; j < 8; j++) {
        s[j]  += __shfl_down_sync(0xffffffffu, s[j], 16);
        s2[j] += __shfl_down_sync(0xffffffffu, s2[j], 16);
        s[j]  += __shfl_down_sync(0xffffffffu, s[j], 8);
        s2[j] += __shfl_down_sync(0xffffffffu, s2[j], 8);
    }
    if ((t & 31) < 8) {
#pragma unroll
        for (int j = 0; j < 8; j++) {
            atomicAdd(&s_sum[cg * 8 + j], s[j]);
            atomicAdd(&s_sq[cg * 8 + j], s2[j]);
        }
    }
    __syncthreads();
    if (t < 64) {
        atomicAdd(&g_sum[t], s_sum[t]);
        atomicAdd(&g_sumsq[t], s_sq[t]);
    }
}

// ---------------- 4: BN affine + ReLU + residual ----------------
__global__ void __launch_bounds__(256) out_kernel(const float* __restrict__ x,
                                                  const float* __restrict__ gamma,
                                                  const float* __restrict__ beta,
                                                  float* __restrict__ out, int n) {
    __shared__ float sc[64], sh[64];
    int t = threadIdx.x;
    if (t < 64) {
        float invn = 1.0f / (float)n;
        float mean = g_sum[t] * invn;
        float var = g_sumsq[t] * invn - mean * mean;
        float s = gamma[t] * rsqrtf(var + 1e-5f);
        sc[t] = s;
        sh[t] = beta[t] - mean * s;
    }
    __syncthreads();
    const uint2* A2 = reinterpret_cast<const uint2*>(g_Agg);
    const float4* X4 = reinterpret_cast<const float4*>(x);
    float4* O4 = reinterpret_cast<float4*>(out);
    int total = n * 16;
    for (int i = blockIdx.x * blockDim.x + t; i < total; i += gridDim.x * blockDim.x) {
        int col = (i & 15) * 4;
        uint2 au = A2[i];
        __half2 al = reinterpret_cast<__half2&>(au.x);
        __half2 ah = reinterpret_cast<__half2&>(au.y);
        float2 a01 = __half22float2(al);
        float2 a23 = __half22float2(ah);
        float4 xv = X4[i];
        float4 o;
        o.x = fmaxf(a01.x * sc[col + 0] + sh[col + 0], 0.0f) + xv.x;
        o.y = fmaxf(a01.y * sc[col + 1] + sh[col + 1], 0.0f) + xv.y;
        o.z = fmaxf(a23.x * sc[col + 2] + sh[col + 2], 0.0f) + xv.z;
        o.w = fmaxf(a23.y * sc[col + 3] + sh[col + 3], 0.0f) + xv.w;
        O4[i] = o;
    }
}

// ---------------- launch ----------------
extern "C" void kernel_launch(void* const* d_in, const int* in_sizes, int n_in,
                              void* d_out, int out_size) {
    const float* x     = (const float*)d_in[0];
    const void*  ei    = d_in[1];
    const float* Wk    = (const float*)d_in[2];
    const float* bk    = (const float*)d_in[3];
    const float* Wq    = (const float*)d_in[4];
    const float* bq    = (const float*)d_in[5];
    const float* Wv    = (const float*)d_in[6];
    const float* bv    = (const float*)d_in[7];
    const float* Ws    = (const float*)d_in[8];
    const float* bs    = (const float*)d_in[9];
    const float* gamma = (const float*)d_in[10];
    const float* beta  = (const float*)d_in[11];

    int n = in_sizes[0] / DF;
    int e = in_sizes[1] / 2;

    static bool attr_done = false;
    if (!attr_done) {
        cudaFuncSetAttribute(gemm_kernel, cudaFuncAttributeMaxDynamicSharedMemorySize,
                             GEMM_SMEM);
        attr_done = true;
    }

    prep_kernel<<<64, 256>>>((const int*)ei, e, Wk, Wq, Wv, Ws);

    gemm_kernel<<<(n + 63) / 64, 256, GEMM_SMEM>>>(x, bk, bq, bv, bs, n);

    int pairs = (e + 1) / 2;
    edge_kernel<<<(pairs * 8 + 255) / 256, 256>>>(ei, e);
    stats_kernel<<<512, 256>>>(n);
    out_kernel<<<2048, 256>>>(x, gamma, beta, (float*)d_out, n);
}

// round 17
// speedup vs baseline: 2.9266x; 1.0047x over previous
#include <cuda_runtime.h>
#include <cuda_fp16.h>
#include <cstdint>

#define NMAX 100000
#define EMAX 1600000
#define DF 64

// ---------------- device scratch (no allocations allowed) ----------------
__device__ __half g_Kh[NMAX * DF];
__device__ __half g_Qh[NMAX * DF];
__device__ __half g_Vh[NMAX * DF];
__device__ __half g_Agg[NMAX * DF];   // fp16: skip (from GEMM) + messages (RED target)
__device__ __half g_Wh[4 * DF * DF];  // fp16 weights, [m][c][k] row-major
__device__ float  g_sum[DF];
__device__ float  g_sumsq[DF];
__device__ int    g_is64;

// ---------------- mma helpers ----------------
__device__ __forceinline__ void ldsm_x4(unsigned* r, uint32_t addr) {
    asm volatile("ldmatrix.sync.aligned.m8n8.x4.shared.b16 {%0,%1,%2,%3}, [%4];\n"
                 : "=r"(r[0]), "=r"(r[1]), "=r"(r[2]), "=r"(r[3]) : "r"(addr));
}
__device__ __forceinline__ void mma16816(float* d, const unsigned* a, const unsigned* b) {
    asm volatile(
        "mma.sync.aligned.m16n8k16.row.col.f32.f16.f16.f32 "
        "{%0,%1,%2,%3}, {%4,%5,%6,%7}, {%8,%9}, {%0,%1,%2,%3};\n"
        : "+f"(d[0]), "+f"(d[1]), "+f"(d[2]), "+f"(d[3])
        : "r"(a[0]), "r"(a[1]), "r"(a[2]), "r"(a[3]), "r"(b[0]), "r"(b[1]));
}
// 16B fp16 vector reduction (sm_90+): 8 halves per lane, one instruction.
__device__ __forceinline__ void red_v4f16x2(__half* p, unsigned a0, unsigned a1,
                                            unsigned a2, unsigned a3) {
    asm volatile("red.global.add.noftz.v4.f16x2 [%0], {%1,%2,%3,%4};"
                 :: "l"(p), "r"(a0), "r"(a1), "r"(a2), "r"(a3) : "memory");
}

// ---------------- 0: prep — zero BN sums, detect index width, weights -> fp16 ----------
__global__ void prep_kernel(const int* __restrict__ ei32, int e,
                            const float* __restrict__ Wk, const float* __restrict__ Wq,
                            const float* __restrict__ Wv, const float* __restrict__ Ws) {
    int gt = blockIdx.x * blockDim.x + threadIdx.x;
    if (gt < DF) { g_sum[gt] = 0.0f; g_sumsq[gt] = 0.0f; }
    if (gt < 4 * DF * DF) {
        int m = gt >> 12;
        int i = gt & 4095;
        const float* W = (m == 0) ? Wk : (m == 1) ? Wq : (m == 2) ? Wv : Ws;
        g_Wh[gt] = __float2half(W[i]);
    }
    if (blockIdx.x == 0) {
        __shared__ int any;
        int t = threadIdx.x;
        if (t == 0) any = 0;
        __syncthreads();
        int nz = 0;
        for (int i = t; i < 1024; i += blockDim.x)
            if (i < e) nz |= ei32[2 * i + 1];
        if (nz) atomicOr(&any, 1);
        __syncthreads();
        if (t == 0) g_is64 = any ? 0 : 1;
    }
}

// ---------------- 1: tensor-core GEMM: all 4 matrices, one launch, one sync ------------
// Block: 128 rows, 512 threads (16 warps = two 8-warp groups; wg = w>>3 picks the
// 64-row half). Weights staged ONCE per 128 rows; single __syncthreads. Per-group
// warp task = 16 rows x 32 cols across all 4 matrices (rt = (w&7)>>1, ch = w&1).
// A-fragments loaded once, reused for the 4 matrices. All outputs fp16
// (m=3 -> g_Agg seeds the skip for the fp16 RED accumulator).
#define GEMM_SMEM ((128 * 72 + 4 * 64 * 72) * 2)

__global__ void __launch_bounds__(512) gemm_kernel(const float* __restrict__ x,
                                                   const float* __restrict__ bk,
                                                   const float* __restrict__ bq,
                                                   const float* __restrict__ bv,
                                                   const float* __restrict__ bs,
                                                   int n) {
    extern __shared__ __half smh[];
    __half* xs = smh;                 // [128][72]
    __half* ws = smh + 128 * 72;      // [4][64][72]
    int t = threadIdx.x;
    int lane = t & 31, w = t >> 5;
    int row0 = blockIdx.x * 128;

    // Stage x (128 rows) -> fp16 (zero-fill OOB rows)
    for (int idx = t; idx < 128 * 16; idx += 512) {
        int r = idx >> 4, k4 = idx & 15;
        float4 v = make_float4(0.f, 0.f, 0.f, 0.f);
        if (row0 + r < n)
            v = reinterpret_cast<const float4*>(x + (size_t)(row0 + r) * DF)[k4];
        __half2 h0 = __floats2half2_rn(v.x, v.y);
        __half2 h1 = __floats2half2_rn(v.z, v.w);
        uint2 u;
        u.x = reinterpret_cast<unsigned&>(h0);
        u.y = reinterpret_cast<unsigned&>(h1);
        *reinterpret_cast<uint2*>(&xs[r * 72 + k4 * 4]) = u;
    }
    // Stage all 4 weight matrices
    for (int idx = t; idx < 4 * 64 * 8; idx += 512) {
        int mr = idx >> 3, k8 = idx & 7;
        uint4 v = *reinterpret_cast<const uint4*>(&g_Wh[mr * DF + k8 * 8]);
        *reinterpret_cast<uint4*>(&ws[mr * 72 + k8 * 8]) = v;
    }
    __syncthreads();

    int wg = w >> 3;          // 64-row half 0..1
    int wl = w & 7;
    int rt = wl >> 1;         // row-group 0..3 (16 rows each)
    int ch = wl & 1;          // col-half 0..1 (32 cols each)
    int a_row = lane & 15;
    int a_ch  = lane >> 4;
    int b_row = lane & 7;
    int b_ch  = (lane >> 3) & 1;
    int b_nt  = lane >> 4;
    int rbase = wg * 64 + rt * 16;

    // A fragments: 1 m16 tile x 4 ks, loaded once, reused for all 4 matrices
    unsigned a[4][4];
#pragma unroll
    for (int ks = 0; ks < 4; ks++) {
        uint32_t addr = (uint32_t)__cvta_generic_to_shared(
            &xs[(rbase + a_row) * 72 + ks * 16 + a_ch * 8]);
        ldsm_x4(a[ks], addr);
    }

    int ra = (lane >> 2);
    int coff = (lane & 3) * 2;

#pragma unroll
    for (int m = 0; m < 4; m++) {
        float acc[4][4];
#pragma unroll
        for (int j = 0; j < 4; j++)
#pragma unroll
            for (int c = 0; c < 4; c++) acc[j][c] = 0.0f;

#pragma unroll
        for (int ks = 0; ks < 4; ks++) {
            unsigned b[4][2];
#pragma unroll
            for (int h = 0; h < 2; h++) {
                uint32_t addr = (uint32_t)__cvta_generic_to_shared(
                    &ws[(m * 64 + ch * 32 + h * 16 + 8 * b_nt + b_row) * 72 +
                        ks * 16 + b_ch * 8]);
                unsigned r4[4];
                ldsm_x4(r4, addr);
                b[2 * h][0] = r4[0];     b[2 * h][1] = r4[1];
                b[2 * h + 1][0] = r4[2]; b[2 * h + 1][1] = r4[3];
            }
#pragma unroll
            for (int j = 0; j < 4; j++)
                mma16816(acc[j], a[ks], b[j]);
        }

        const float* bp = (m == 0) ? bk : (m == 1) ? bq : (m == 2) ? bv : bs;
        __half* outh = (m == 0) ? g_Kh : (m == 1) ? g_Qh : (m == 2) ? g_Vh : g_Agg;
        int r0g = row0 + rbase + ra;
#pragma unroll
        for (int j = 0; j < 4; j++) {
            int col = ch * 32 + j * 8 + coff;
            float bb0 = __ldg(&bp[col]);
            float bb1 = __ldg(&bp[col + 1]);
            float v0 = acc[j][0] + bb0, v1 = acc[j][1] + bb1;
            float v2 = acc[j][2] + bb0, v3 = acc[j][3] + bb1;
            if (r0g < n)
                *reinterpret_cast<__half2*>(outh + (size_t)r0g * DF + col) =
                    __floats2half2_rn(v0, v1);
            if (r0g + 8 < n)
                *reinterpret_cast<__half2*>(outh + (size_t)(r0g + 8) * DF + col) =
                    __floats2half2_rn(v2, v3);
        }
    }
}

// ---------------- 2: edge gather (fp16) + gate + fp16 VECTOR red scatter --------------
// 8 threads per edge-PAIR: each thread handles features c*8..c*8+7 of TWO
// consecutive edges; 6 gathers issued before any compute. One 16B red.v4.f16x2
// per edge per thread into g_Agg (which already holds the skip).
__global__ void __launch_bounds__(256) edge_kernel(const void* __restrict__ ei, int e) {
    int idx = blockIdx.x * blockDim.x + threadIdx.x;
    int pair = idx >> 3;
    int c = idx & 7;
    int ed0 = pair * 2;
    if (ed0 >= e) return;
    int ed1 = ed0 + 1;
    bool has1 = (ed1 < e);

    int s0, d0, s1, d1;
    if (g_is64) {
        const long long* p = (const long long*)ei;
        s0 = (int)p[ed0]; d0 = (int)p[e + ed0];
        s1 = has1 ? (int)p[ed1] : s0;
        d1 = has1 ? (int)p[e + ed1] : d0;
    } else {
        const int* p = (const int*)ei;
        s0 = p[ed0]; d0 = p[e + ed0];
        s1 = has1 ? p[ed1] : s0;
        d1 = has1 ? p[e + ed1] : d0;
    }

    const uint4* Kp = reinterpret_cast<const uint4*>(g_Kh);
    const uint4* Qp = reinterpret_cast<const uint4*>(g_Qh);
    const uint4* Vp = reinterpret_cast<const uint4*>(g_Vh);
    uint4 kr0 = __ldg(&Kp[(size_t)d0 * 8 + c]);
    uint4 qr0 = __ldg(&Qp[(size_t)s0 * 8 + c]);
    uint4 vr0 = __ldg(&Vp[(size_t)s0 * 8 + c]);
    uint4 kr1 = __ldg(&Kp[(size_t)d1 * 8 + c]);
    uint4 qr1 = __ldg(&Qp[(size_t)s1 * 8 + c]);
    uint4 vr1 = __ldg(&Vp[(size_t)s1 * 8 + c]);

    {
        const __half2* kh = reinterpret_cast<const __half2*>(&kr0);
        const __half2* qh = reinterpret_cast<const __half2*>(&qr0);
        const __half2* vh = reinterpret_cast<const __half2*>(&vr0);
        unsigned a[4];
#pragma unroll
        for (int p = 0; p < 4; p++) {
            float2 kf = __half22float2(kh[p]);
            float2 qf = __half22float2(qh[p]);
            float2 vf = __half22float2(vh[p]);
            float m0 = __fdividef(vf.x, 1.0f + __expf(-(kf.x + qf.x)));
            float m1 = __fdividef(vf.y, 1.0f + __expf(-(kf.y + qf.y)));
            __half2 h = __floats2half2_rn(m0, m1);
            a[p] = reinterpret_cast<unsigned&>(h);
        }
        red_v4f16x2(g_Agg + (size_t)d0 * DF + c * 8, a[0], a[1], a[2], a[3]);
    }
    if (has1) {
        const __half2* kh = reinterpret_cast<const __half2*>(&kr1);
        const __half2* qh = reinterpret_cast<const __half2*>(&qr1);
        const __half2* vh = reinterpret_cast<const __half2*>(&vr1);
        unsigned a[4];
#pragma unroll
        for (int p = 0; p < 4; p++) {
            float2 kf = __half22float2(kh[p]);
            float2 qf = __half22float2(qh[p]);
            float2 vf = __half22float2(vh[p]);
            float m0 = __fdividef(vf.x, 1.0f + __expf(-(kf.x + qf.x)));
            float m1 = __fdividef(vf.y, 1.0f + __expf(-(kf.y + qf.y)));
            __half2 h = __floats2half2_rn(m0, m1);
            a[p] = reinterpret_cast<unsigned&>(h);
        }
        red_v4f16x2(g_Agg + (size_t)d1 * DF + c * 8, a[0], a[1], a[2], a[3]);
    }
}

// ---------------- 3: BatchNorm statistics — vectorized 16B loads, 2-row ILP ----------
// Thread: cg = t&7 owns cols cg*8..cg*8+7; rows r and r+gridDim.x*32 loaded per
// iteration (2 outstanding 16B loads). Warp-reduce lanes sharing cg, then lanes
// 0..7 atomic-add 8 cols each to smem; one global atomic per column per block.
__global__ void __launch_bounds__(256) stats_kernel(int n) {
    __shared__ float s_sum[64], s_sq[64];
    int t = threadIdx.x;
    if (t < 64) { s_sum[t] = 0.0f; s_sq[t] = 0.0f; }
    __syncthreads();

    int cg = t & 7;
    int rowoff = t >> 3;   // 0..31
    int stride = gridDim.x * 32;
    float s[8], s2[8];
#pragma unroll
    for (int j = 0; j < 8; j++) { s[j] = 0.0f; s2[j] = 0.0f; }

    for (int r = blockIdx.x * 32 + rowoff; r < n; r += 2 * stride) {
        uint4 v0 = *(reinterpret_cast<const uint4*>(g_Agg) + (size_t)r * 8 + cg);
        int r1 = r + stride;
        uint4 v1 = (r1 < n)
            ? *(reinterpret_cast<const uint4*>(g_Agg) + (size_t)r1 * 8 + cg)
            : make_uint4(0, 0, 0, 0);
        const __half2* h0 = reinterpret_cast<const __half2*>(&v0);
        const __half2* h1 = reinterpret_cast<const __half2*>(&v1);
#pragma unroll
        for (int p = 0; p < 4; p++) {
            float2 f0 = __half22float2(h0[p]);
            float2 f1 = __half22float2(h1[p]);
            s[2 * p]     += f0.x + f1.x;
            s2[2 * p]    += f0.x * f0.x + f1.x * f1.x;
            s[2 * p + 1] += f0.y + f1.y;
            s2[2 * p + 1]+= f0.y * f0.y + f1.y * f1.y;
        }
    }
    // Reduce across the 4 lanes in this warp sharing cg (lanes cg, cg+8, cg+16, cg+24)
#pragma unroll
    for (int j = 0; j < 8; j++) {
        s[j]  += __shfl_down_sync(0xffffffffu, s[j], 16);
        s2[j] += __shfl_down_sync(0xffffffffu, s2[j], 16);
        s[j]  += __shfl_down_sync(0xffffffffu, s[j], 8);
        s2[j] += __shfl_down_sync(0xffffffffu, s2[j], 8);
    }
    if ((t & 31) < 8) {
#pragma unroll
        for (int j = 0; j < 8; j++) {
            atomicAdd(&s_sum[cg * 8 + j], s[j]);
            atomicAdd(&s_sq[cg * 8 + j], s2[j]);
        }
    }
    __syncthreads();
    if (t < 64) {
        atomicAdd(&g_sum[t], s_sum[t]);
        atomicAdd(&g_sumsq[t], s_sq[t]);
    }
}

// ---------------- 4: BN affine + ReLU + residual ----------------
__global__ void __launch_bounds__(256) out_kernel(const float* __restrict__ x,
                                                  const float* __restrict__ gamma,
                                                  const float* __restrict__ beta,
                                                  float* __restrict__ out, int n) {
    __shared__ float sc[64], sh[64];
    int t = threadIdx.x;
    if (t < 64) {
        float invn = 1.0f / (float)n;
        float mean = g_sum[t] * invn;
        float var = g_sumsq[t] * invn - mean * mean;
        float s = gamma[t] * rsqrtf(var + 1e-5f);
        sc[t] = s;
        sh[t] = beta[t] - mean * s;
    }
    __syncthreads();
    const uint2* A2 = reinterpret_cast<const uint2*>(g_Agg);
    const float4* X4 = reinterpret_cast<const float4*>(x);
    float4* O4 = reinterpret_cast<float4*>(out);
    int total = n * 16;
    for (int i = blockIdx.x * blockDim.x + t; i < total; i += gridDim.x * blockDim.x) {
        int col = (i & 15) * 4;
        uint2 au = A2[i];
        __half2 al = reinterpret_cast<__half2&>(au.x);
        __half2 ah = reinterpret_cast<__half2&>(au.y);
        float2 a01 = __half22float2(al);
        float2 a23 = __half22float2(ah);
        float4 xv = X4[i];
        float4 o;
        o.x = fmaxf(a01.x * sc[col + 0] + sh[col + 0], 0.0f) + xv.x;
        o.y = fmaxf(a01.y * sc[col + 1] + sh[col + 1], 0.0f) + xv.y;
        o.z = fmaxf(a23.x * sc[col + 2] + sh[col + 2], 0.0f) + xv.z;
        o.w = fmaxf(a23.y * sc[col + 3] + sh[col + 3], 0.0f) + xv.w;
        O4[i] = o;
    }
}

// ---------------- launch ----------------
extern "C" void kernel_launch(void* const* d_in, const int* in_sizes, int n_in,
                              void* d_out, int out_size) {
    const float* x     = (const float*)d_in[0];
    const void*  ei    = d_in[1];
    const float* Wk    = (const float*)d_in[2];
    const float* bk    = (const float*)d_in[3];
    const float* Wq    = (const float*)d_in[4];
    const float* bq    = (const float*)d_in[5];
    const float* Wv    = (const float*)d_in[6];
    const float* bv    = (const float*)d_in[7];
    const float* Ws    = (const float*)d_in[8];
    const float* bs    = (const float*)d_in[9];
    const float* gamma = (const float*)d_in[10];
    const float* beta  = (const float*)d_in[11];

    int n = in_sizes[0] / DF;
    int e = in_sizes[1] / 2;

    static bool attr_done = false;
    if (!attr_done) {
        cudaFuncSetAttribute(gemm_kernel, cudaFuncAttributeMaxDynamicSharedMemorySize,
                             GEMM_SMEM);
        attr_done = true;
    }

    prep_kernel<<<64, 256>>>((const int*)ei, e, Wk, Wq, Wv, Ws);

    gemm_kernel<<<(n + 127) / 128, 512, GEMM_SMEM>>>(x, bk, bq, bv, bs, n);

    int pairs = (e + 1) / 2;
    edge_kernel<<<(pairs * 8 + 255) / 256, 256>>>(ei, e);
    stats_kernel<<<512, 256>>>(n);
    out_kernel<<<2048, 256>>>(x, gamma, beta, (float*)d_out, n);
}